// round 14
// baseline (speedup 1.0000x reference)
#include <cuda_runtime.h>
#include <cuda_bf16.h>
#include <math.h>
#include <stdint.h>

#define NP   120000
#define DIM  256
#define BATCH 2
#define NH   8
#define NOUT 20
#define ZD 60
#define YD 45
#define XD 4
#define GQ 10800
#define SQ 21600
#define ZE 12
#define YE 24
#define XE 2
#define GK 576
#define SK 1152
#define NF 42
#define PEC 252

__device__ unsigned g_pool_key[SQ * DIM];
__device__ unsigned long long g_emb_key[SK * DIM];
__device__ int      g_mask_q[SQ];
__device__ int      g_mask_k[SK];
__device__ int      g_segq[NP];
__device__ int      g_segk[NP];
__device__ float    g_o2[(size_t)SQ * DIM];
__device__ float    g_mhca[(size_t)SQ * DIM];
__device__ float    g_invt[64];
__device__ float    g_bq[DIM];
__device__ float    g_bk[DIM];
__device__ float    g_bv[DIM];
__device__ __nv_bfloat16 g_featH[(size_t)NP * DIM];
__device__ __nv_bfloat16 g_featL[(size_t)NP * DIM];
__device__ __nv_bfloat16 g_wH[6 * 65536];
__device__ __nv_bfloat16 g_wL[6 * 65536];
__device__ __nv_bfloat16 g_qinH[(size_t)SQ * DIM];
__device__ __nv_bfloat16 g_qinL[(size_t)SQ * DIM];
__device__ __nv_bfloat16 g_kvH[SK * DIM];
__device__ __nv_bfloat16 g_kvL[SK * DIM];
__device__ __nv_bfloat16 g_qpH[(size_t)SQ * DIM];
__device__ __nv_bfloat16 g_qpL[(size_t)SQ * DIM];
__device__ __nv_bfloat16 g_oaH[(size_t)SQ * DIM];
__device__ __nv_bfloat16 g_oaL[(size_t)SQ * DIM];
__device__ __nv_bfloat16 g_k16h[16 * 32 * 576];
__device__ __nv_bfloat16 g_k16l[16 * 32 * 576];
__device__ __nv_bfloat16 g_v16h[16 * 576 * 32];
__device__ __nv_bfloat16 g_v16l[16 * 576 * 32];

__device__ __forceinline__ unsigned fenc(float f) {
    unsigned u = __float_as_uint(f);
    return (u & 0x80000000u) ? ~u : (u | 0x80000000u);
}
__device__ __forceinline__ float fdec(unsigned k) {
    return __uint_as_float((k & 0x80000000u) ? (k ^ 0x80000000u) : ~k);
}

__device__ __forceinline__ uint32_t sptr(const void* p) {
    return (uint32_t)__cvta_generic_to_shared(p);
}

#define LDSM_X4(r, addr) \
    asm volatile("ldmatrix.sync.aligned.m8n8.x4.shared.b16 {%0,%1,%2,%3}, [%4];" \
        : "=r"((r)[0]), "=r"((r)[1]), "=r"((r)[2]), "=r"((r)[3]) : "r"(addr))

#define LDSM_X4_T(r, addr) \
    asm volatile("ldmatrix.sync.aligned.m8n8.x4.trans.shared.b16 {%0,%1,%2,%3}, [%4];" \
        : "=r"((r)[0]), "=r"((r)[1]), "=r"((r)[2]), "=r"((r)[3]) : "r"(addr))

__device__ __forceinline__ void mma16816(float* c, const uint32_t* a, uint32_t b0, uint32_t b1) {
    asm volatile(
        "mma.sync.aligned.m16n8k16.row.col.f32.bf16.bf16.f32 "
        "{%0,%1,%2,%3}, {%4,%5,%6,%7}, {%8,%9}, {%0,%1,%2,%3};"
        : "+f"(c[0]), "+f"(c[1]), "+f"(c[2]), "+f"(c[3])
        : "r"(a[0]), "r"(a[1]), "r"(a[2]), "r"(a[3]), "r"(b0), "r"(b1));
}

#define CP16(dst, src) \
    asm volatile("cp.async.cg.shared.global [%0], [%1], 16;\n" :: "r"(dst), "l"(src))
#define CP_COMMIT asm volatile("cp.async.commit_group;\n" ::: "memory")
#define CP_WAIT2 asm volatile("cp.async.wait_group 2;\n" ::: "memory")
#define CP_WAIT1 asm volatile("cp.async.wait_group 1;\n" ::: "memory")
#define CP_WAIT0 asm volatile("cp.async.wait_group 0;\n" ::: "memory")

__device__ __forceinline__ void split_bf16(float v, __nv_bfloat16& h, __nv_bfloat16& l) {
    h = __float2bfloat16(v);
    l = __float2bfloat16(v - __bfloat162float(h));
}

__device__ __forceinline__ void split2pack(float a, float b, uint32_t& hi, uint32_t& lo) {
    __nv_bfloat16 ha = __float2bfloat16(a), hb = __float2bfloat16(b);
    __nv_bfloat16 la = __float2bfloat16(a - __bfloat162float(ha));
    __nv_bfloat16 lb = __float2bfloat16(b - __bfloat162float(hb));
    __nv_bfloat162 th(ha, hb), tl(la, lb);
    hi = *(uint32_t*)&th;
    lo = *(uint32_t*)&tl;
}

// ---------------- merged split + prep kernel ----------------
#define FEAT_BLOCKS 30000
#define W_BLOCKS 384
#define PREP_BLOCKS 469
__global__ void split_prep_k(const float* __restrict__ feat,
                             const float* __restrict__ w0, const float* __restrict__ w1,
                             const float* __restrict__ w2, const float* __restrict__ w3,
                             const float* __restrict__ w4, const float* __restrict__ w5,
                             const float* __restrict__ bq, const float* __restrict__ bk,
                             const float* __restrict__ bv, const int* __restrict__ ind) {
    int bx = blockIdx.x;
    int t = threadIdx.x;
    if (bx < FEAT_BLOCKS) {
        size_t i = (size_t)bx * 256 + t;
        float4 v = ((const float4*)feat)[i];
        __nv_bfloat16 hx, lx, hy, ly, hz, lz, hw, lw;
        split_bf16(v.x, hx, lx); split_bf16(v.y, hy, ly);
        split_bf16(v.z, hz, lz); split_bf16(v.w, hw, lw);
        ((__nv_bfloat162*)g_featH)[i * 2]     = __nv_bfloat162(hx, hy);
        ((__nv_bfloat162*)g_featH)[i * 2 + 1] = __nv_bfloat162(hz, hw);
        ((__nv_bfloat162*)g_featL)[i * 2]     = __nv_bfloat162(lx, ly);
        ((__nv_bfloat162*)g_featL)[i * 2 + 1] = __nv_bfloat162(lz, lw);
    } else if (bx < FEAT_BLOCKS + W_BLOCKS) {
        int i = (bx - FEAT_BLOCKS) * 256 + t;
        int which = i >> 14;
        int off = i & 16383;
        const float* src = which == 0 ? w0 : which == 1 ? w1 : which == 2 ? w2
                         : which == 3 ? w3 : which == 4 ? w4 : w5;
        float4 v = ((const float4*)src)[off];
        __nv_bfloat16 hx, lx, hy, ly, hz, lz, hw, lw;
        split_bf16(v.x, hx, lx); split_bf16(v.y, hy, ly);
        split_bf16(v.z, hz, lz); split_bf16(v.w, hw, lw);
        ((__nv_bfloat162*)g_wH)[i * 2]     = __nv_bfloat162(hx, hy);
        ((__nv_bfloat162*)g_wH)[i * 2 + 1] = __nv_bfloat162(hz, hw);
        ((__nv_bfloat162*)g_wL)[i * 2]     = __nv_bfloat162(lx, ly);
        ((__nv_bfloat162*)g_wL)[i * 2 + 1] = __nv_bfloat162(lz, lw);
    } else if (bx == FEAT_BLOCKS + W_BLOCKS) {
        if (t < NF) g_invt[t] = 1.0f / powf(10000.0f, (float)t / (float)NF);
        g_bq[t] = bq[t];
        g_bk[t] = bk[t];
        g_bv[t] = bv[t];
    } else {
        int i = (bx - FEAT_BLOCKS - W_BLOCKS - 1) * 256 + t;
        if (i >= NP) return;
        int b = ind[i * 4 + 0];
        int z = ind[i * 4 + 1];
        int y = ind[i * 4 + 2];
        int x = ind[i * 4 + 3];
        int sq = ((b * ZD + z / 8) * YD + y / 8) * XD + x / 8;
        int sk = ((b * ZE + z / 40) * YE + y / 15) * XE + x / 16;
        g_segq[i] = sq;
        g_segk[i] = sk;
        g_mask_q[sq] = 1;
        g_mask_k[sk] = 1;
    }
}

// ================= 3-stage pipelined bf16x3 MMA GEMM core =====================
#define AP 40
#define BP 136
#define SA3_BYTES (3 * 2 * 128 * AP * 2)
#define SB3_BYTES (3 * 2 * 32 * BP * 2)
#define GEMM_SMEM (SA3_BYTES + SB3_BYTES)

__device__ __forceinline__ __nv_bfloat16* pA(__nv_bfloat16* b, int st, int mat, int r) {
    return b + ((st * 2 + mat) * 128 + r) * AP;
}
__device__ __forceinline__ __nv_bfloat16* pB(__nv_bfloat16* b, int st, int mat, int r) {
    return b + ((st * 2 + mat) * 32 + r) * BP;
}

__device__ __forceinline__ void gemm_core(char* dsm, int t,
                                          const __nv_bfloat16* __restrict__ Ah,
                                          const __nv_bfloat16* __restrict__ Al,
                                          const __nv_bfloat16* __restrict__ Whp,
                                          const __nv_bfloat16* __restrict__ Wlp,
                                          int m0, int c0, int M, float acc[4][4][4]) {
    __nv_bfloat16* sA = (__nv_bfloat16*)dsm;
    __nv_bfloat16* sB = (__nv_bfloat16*)(dsm + SA3_BYTES);
    int wid = t >> 5, lane = t & 31;
    int wm = wid >> 2, wn = wid & 3;

    auto copyA = [&](int st, int ch) {
        int k0 = ch * 32;
#pragma unroll
        for (int i = 0; i < 2; i++) {
            int op = t * 2 + i;
            int r = op >> 2, seg = op & 3;
            int rowc = m0 + r;
            if (rowc >= M) rowc = M - 1;
            size_t src = (size_t)rowc * 256 + k0 + seg * 8;
            CP16(sptr(pA(sA, st, 0, r) + seg * 8), Ah + src);
            CP16(sptr(pA(sA, st, 1, r) + seg * 8), Al + src);
        }
    };
    auto copyB = [&](int st, int ch) {
        int k0 = ch * 32;
        int r = t >> 3;
#pragma unroll
        for (int q = 0; q < 2; q++) {
            int seg = (t & 7) + q * 8;
            size_t src = (size_t)(k0 + r) * 256 + c0 + seg * 8;
            CP16(sptr(pB(sB, st, 0, r) + seg * 8), Whp + src);
            CP16(sptr(pB(sB, st, 1, r) + seg * 8), Wlp + src);
        }
    };

    copyA(0, 0); copyB(0, 0); CP_COMMIT;
    copyA(1, 1); copyB(1, 1); CP_COMMIT;

    for (int ch = 0; ch < 8; ch++) {
        if (ch < 6) {
            int st2 = (ch + 2) % 3;
            copyA(st2, ch + 2);
            copyB(st2, ch + 2);
            CP_COMMIT;
            CP_WAIT2;
        } else if (ch == 6) {
            CP_WAIT1;
        } else {
            CP_WAIT0;
        }
        __syncthreads();
        int st = ch % 3;
#pragma unroll
        for (int ks = 0; ks < 2; ks++) {
            int arow = wm * 64 + (lane & 15);
            int akc = ks * 16 + ((lane & 16) ? 8 : 0);
            int bkr = ks * 16 + (lane & 15);
            int bnc = wn * 32 + ((lane & 16) ? 8 : 0);

            uint32_t af[4][4], bh[8], bl[8];
#pragma unroll
            for (int mt = 0; mt < 4; mt++)
                LDSM_X4(af[mt], sptr(pA(sA, st, 0, arow + mt * 16) + akc));
            LDSM_X4_T(bh,     sptr(pB(sB, st, 0, bkr) + bnc));
            LDSM_X4_T(bh + 4, sptr(pB(sB, st, 0, bkr) + bnc + 16));
            LDSM_X4_T(bl,     sptr(pB(sB, st, 1, bkr) + bnc));
            LDSM_X4_T(bl + 4, sptr(pB(sB, st, 1, bkr) + bnc + 16));

#pragma unroll
            for (int mt = 0; mt < 4; mt++) {
#pragma unroll
                for (int nt = 0; nt < 4; nt++) {
                    mma16816(acc[mt][nt], af[mt], bh[nt * 2], bh[nt * 2 + 1]);
                    mma16816(acc[mt][nt], af[mt], bl[nt * 2], bl[nt * 2 + 1]);
                }
            }
#pragma unroll
            for (int mt = 0; mt < 4; mt++)
                LDSM_X4(af[mt], sptr(pA(sA, st, 1, arow + mt * 16) + akc));
#pragma unroll
            for (int mt = 0; mt < 4; mt++) {
#pragma unroll
                for (int nt = 0; nt < 4; nt++)
                    mma16816(acc[mt][nt], af[mt], bh[nt * 2], bh[nt * 2 + 1]);
            }
        }
        __syncthreads();
    }
}

// MODE 10: fused pool/emb; MODE 0: fp32 store.
template <int MODE>
__global__ __launch_bounds__(256, 2) void bf_gemm(
    const __nv_bfloat16* __restrict__ Ah, const __nv_bfloat16* __restrict__ Al,
    const __nv_bfloat16* __restrict__ WhA, const __nv_bfloat16* __restrict__ WlA,
    const float* __restrict__ biasA,
    const __nv_bfloat16* __restrict__ WhB, const __nv_bfloat16* __restrict__ WlB,
    const float* __restrict__ biasB,
    float* __restrict__ Cout,
    unsigned* __restrict__ keyP, const int* __restrict__ segP,
    unsigned long long* __restrict__ keyE, const int* __restrict__ segE,
    int M)
{
    extern __shared__ char dsm[];
    int t = threadIdx.x, wid = t >> 5, lane = t & 31;
    int wm = wid >> 2, wn = wid & 3;
    int m0 = blockIdx.y * 128;

    bool isPool = false;
    const __nv_bfloat16 *Whp = WhA, *Wlp = WlA;
    const float* bp = biasA;
    int c0;
    if (MODE == 10) {
        isPool = ((blockIdx.x >> 1) == 0);
        if (!isPool) { Whp = WhB; Wlp = WlB; bp = biasB; }
        c0 = (blockIdx.x & 1) * 128;
    } else {
        c0 = blockIdx.x * 128;
    }

    float acc[4][4][4] = {};
    gemm_core(dsm, t, Ah, Al, Whp, Wlp, m0, c0, M, acc);

    int g = lane >> 2, tid4 = lane & 3;
#pragma unroll
    for (int mt = 0; mt < 4; mt++) {
#pragma unroll
        for (int nt = 0; nt < 4; nt++) {
            int coln = c0 + wn * 32 + nt * 8 + tid4 * 2;
            float b0 = bp[coln], b1 = bp[coln + 1];
#pragma unroll
            for (int half = 0; half < 2; half++) {
                int m = m0 + wm * 64 + mt * 16 + g + half * 8;
                if (m >= M) continue;
                float v0 = acc[mt][nt][half * 2 + 0] + b0;
                float v1 = acc[mt][nt][half * 2 + 1] + b1;
                if (MODE == 0) {
                    Cout[(size_t)m * 256 + coln]     = v0;
                    Cout[(size_t)m * 256 + coln + 1] = v1;
                } else {
                    if (isPool) {
                        int sg = segP[m];
                        atomicMax(&keyP[sg * 256 + coln],     fenc(v0));
                        atomicMax(&keyP[sg * 256 + coln + 1], fenc(v1));
                    } else {
                        int sg = segE[m];
                        unsigned long long p0 = ((unsigned long long)fenc(v0) << 32) | (unsigned)m;
                        unsigned long long p1 = ((unsigned long long)fenc(v1) << 32) | (unsigned)m;
                        atomicMax(&keyE[sg * 256 + coln],     p0);
                        atomicMax(&keyE[sg * 256 + coln + 1], p1);
                    }
                }
            }
        }
    }
}

// ---------------- merged Q+K+V projection (one launch) ----------------
#define QBLKS 338
__global__ __launch_bounds__(256, 2) void qkvproj_k(float qscale) {
    extern __shared__ char dsm[];
    int t = threadIdx.x, wid = t >> 5, lane = t & 31;
    int wm = wid >> 2, wn = wid & 3;
    int bx = blockIdx.x;

    const __nv_bfloat16 *Ahp, *Alp, *Whp, *Wlp;
    const float* bp;
    int m0, c0, M, mode;
    if (bx < QBLKS) {
        mode = 0;
        m0 = (bx >> 1) * 128;
        c0 = (bx & 1) * 128;
        Ahp = g_qinH; Alp = g_qinL;
        Whp = g_wH + 2 * 65536; Wlp = g_wL + 2 * 65536;
        bp = g_bq;
        M = SQ;
    } else {
        int r = bx - QBLKS;
        int sub = r & 3;
        int isV = sub >> 1;
        mode = 1 + isV;
        m0 = (r >> 2) * 128;
        c0 = (sub & 1) * 128;
        Ahp = g_kvH; Alp = g_kvL;
        Whp = g_wH + (3 + isV) * 65536;
        Wlp = g_wL + (3 + isV) * 65536;
        bp = isV ? g_bv : g_bk;
        M = SK;
    }

    float acc[4][4][4] = {};
    gemm_core(dsm, t, Ahp, Alp, Whp, Wlp, m0, c0, M, acc);

    int g = lane >> 2, tid4 = lane & 3;
#pragma unroll
    for (int mt = 0; mt < 4; mt++) {
#pragma unroll
        for (int nt = 0; nt < 4; nt++) {
            int coln = c0 + wn * 32 + nt * 8 + tid4 * 2;
            float b0 = bp[coln], b1 = bp[coln + 1];
#pragma unroll
            for (int half = 0; half < 2; half++) {
                int m = m0 + wm * 64 + mt * 16 + g + half * 8;
                if (m >= M) continue;
                float v0 = acc[mt][nt][half * 2 + 0] + b0;
                float v1 = acc[mt][nt][half * 2 + 1] + b1;
                if (mode == 0) {
                    uint32_t hi, lo;
                    split2pack(v0 * qscale, v1 * qscale, hi, lo);
                    *(uint32_t*)&g_qpH[(size_t)m * 256 + coln] = hi;
                    *(uint32_t*)&g_qpL[(size_t)m * 256 + coln] = lo;
                } else if (mode == 1) {
                    int b_ = m / 576, key = m - b_ * 576;
                    int hh = coln >> 5, d = coln & 31;
                    __nv_bfloat16 H, L;
                    split_bf16(v0, H, L);
                    size_t dst0 = (size_t)((b_ * 8 + hh) * 32 + d) * 576 + key;
                    g_k16h[dst0] = H; g_k16l[dst0] = L;
                    split_bf16(v1, H, L);
                    g_k16h[dst0 + 576] = H; g_k16l[dst0 + 576] = L;
                } else {
                    int b_ = m / 576, key = m - b_ * 576;
                    int hh = coln >> 5, d = coln & 31;
                    __nv_bfloat16 H, L;
                    size_t dst0 = ((size_t)(b_ * 8 + hh) * 576 + key) * 32 + d;
                    split_bf16(v0, H, L);
                    g_v16h[dst0] = H; g_v16l[dst0] = L;
                    split_bf16(v1, H, L);
                    g_v16h[dst0 + 1] = H; g_v16l[dst0 + 1] = L;
                }
            }
        }
    }
}

// ---------------- sine PE ----------------
__device__ __forceinline__ float pe_val(float cz, float cy, float cx, int c) {
    if (c >= PEC) return 0.f;
    int axis = c / (2 * NF);
    int r = c - axis * (2 * NF);
    int j = r < NF ? r : r - NF;
    float coord = (axis == 0) ? cz : (axis == 1) ? cy : cx;
    float spd = (axis == 0) ? 480.f : (axis == 1) ? 360.f : 32.f;
    float ang = coord / spd * 6.283185307179586f * g_invt[j];
    return (r < NF) ? __sinf(ang) : __cosf(ang);
}

// ---------------- merged build: buildq [0,SQ) + (embc+buildkv) [SQ, SQ+SK) ----------------
__global__ void build_k(const int* __restrict__ ind) {
    int bx = blockIdx.x;
    int c = threadIdx.x;
    if (bx < SQ) {
        int s = bx;
        int rem = s % GQ;
        float cz = (float)((rem / (YD * XD)) * 8);
        float cy = (float)(((rem / XD) % YD) * 8);
        float cx = (float)((rem % XD) * 8);
        float base = g_mask_q[s] ? fdec(g_pool_key[(size_t)s * 256 + c]) : 0.f;
        float val = base + pe_val(cz, cy, cx, c);
        size_t idx = (size_t)s * 256 + c;
        __nv_bfloat16 h, l;
        split_bf16(val, h, l);
        g_qinH[idx] = h;
        g_qinL[idx] = l;
    } else {
        __shared__ float rz[256], ry[256], rx[256];
        int s = bx - SQ;
        unsigned long long key = g_emb_key[s * 256 + c];
        int i = (int)(key & 0xFFFFFFFFull);
        int z = ind[i * 4 + 1], y = ind[i * 4 + 2], x = ind[i * 4 + 3];
        rz[c] = (float)(z / 40);
        ry[c] = (float)(y / 15);
        rx[c] = (float)(x / 16);
        __syncthreads();
        for (int o = 128; o > 0; o >>= 1) {
            if (c < o) { rz[c] += rz[c + o]; ry[c] += ry[c + o]; rx[c] += rx[c + o]; }
            __syncthreads();
        }
        float cz = rz[0] * (1.f / 256.f) * 40.f;
        float cy = ry[0] * (1.f / 256.f) * 15.f;
        float cx = rx[0] * (1.f / 256.f) * 16.f;
        float base = g_mask_k[s] ? fdec((unsigned)(key >> 32)) : 0.f;
        float val = base + pe_val(cz, cy, cx, c);
        __nv_bfloat16 h, l;
        split_bf16(val, h, l);
        g_kvH[s * 256 + c] = h;
        g_kvL[s * 256 + c] = l;
    }
}

// ---------------- fused flash attention, 96-key chunks (6 iterations) ----------------
#define QPAD 40
#define KPAD2 104
#define CH 96
#define NCH 6
#define FQ_BYTES (2 * 128 * QPAD * 2)                 // 20480
#define FK_BYTES (2 * 2 * 32 * KPAD2 * 2)             // 26624
#define FV_BYTES (2 * 2 * CH * QPAD * 2)              // 30720
#define FATTN_SMEM (FQ_BYTES + FK_BYTES + FV_BYTES + GK * 4)

__global__ __launch_bounds__(256) void fattn_k(const int* __restrict__ maskk) {
    extern __shared__ char fsm[];
    __nv_bfloat16* sQ = (__nv_bfloat16*)fsm;
    __nv_bfloat16* sK = (__nv_bfloat16*)(fsm + FQ_BYTES);
    __nv_bfloat16* sV = (__nv_bfloat16*)(fsm + FQ_BYTES + FK_BYTES);
    int* smask = (int*)(fsm + FQ_BYTES + FK_BYTES + FV_BYTES);

    int t = threadIdx.x, wid = t >> 5, lane = t & 31;
    int bh = blockIdx.y, b = bh >> 3, h = bh & 7;
    int q0 = blockIdx.x * 128;

    auto sQp = [&](int hl, int r) { return sQ + (hl * 128 + r) * QPAD; };
    auto sKp = [&](int st, int hl, int d) { return sK + ((st * 2 + hl) * 32 + d) * KPAD2; };
    auto sVp = [&](int st, int hl, int k) { return sV + ((st * 2 + hl) * CH + k) * QPAD; };

    auto copyKV = [&](int c, int st) {
        // K chunk [32 d][96 keys]: 384 x 16B per hl
#pragma unroll
        for (int i = 0; i < 2; i++) {
            int op = i * 256 + t;
            if (op < 384) {
                int d = op / 12, ks = (op % 12) * 8;
                size_t srck = (size_t)(bh * 32 + d) * 576 + c * CH + ks;
                CP16(sptr(sKp(st, 0, d) + ks), g_k16h + srck);
                CP16(sptr(sKp(st, 1, d) + ks), g_k16l + srck);
                int key = op >> 2, ds = (op & 3) * 8;
                size_t srcv = (size_t)(bh * 576 + c * CH + key) * 32 + ds;
                CP16(sptr(sVp(st, 0, key) + ds), g_v16h + srcv);
                CP16(sptr(sVp(st, 1, key) + ds), g_v16l + srcv);
            }
        }
    };

    copyKV(0, 0);
    CP_COMMIT;

    {
#pragma unroll
        for (int i = 0; i < 2; i++) {
            int op = t * 2 + i;
            int r = op >> 2, seg = op & 3;
            uint4 vh = make_uint4(0, 0, 0, 0), vl = vh;
            if (q0 + r < GQ) {
                size_t s = (size_t)(b * GQ + q0 + r) * 256 + h * 32 + seg * 8;
                vh = *(const uint4*)&g_qpH[s];
                vl = *(const uint4*)&g_qpL[s];
            }
            *(uint4*)(sQp(0, r) + seg * 8) = vh;
            *(uint4*)(sQp(1, r) + seg * 8) = vl;
        }
    }
    for (int i = t; i < GK; i += 256) smask[i] = maskk[b * GK + i];
    __syncthreads();

    uint32_t qh[2][4], ql[2][4];
    {
        int arow = wid * 16 + (lane & 15);
#pragma unroll
        for (int s = 0; s < 2; s++) {
            int akc = s * 16 + ((lane & 16) ? 8 : 0);
            LDSM_X4(qh[s], sptr(sQp(0, arow) + akc));
            LDSM_X4(ql[s], sptr(sQp(1, arow) + akc));
        }
    }

    float m0r = -INFINITY, m1r = -INFINITY, l0 = 0.f, l1 = 0.f;
    float oacc[4][4] = {};
    int g = lane >> 2, tid4 = lane & 3;
    int bkr = lane & 15;
    int bsel = (lane & 16) ? 8 : 0;

    for (int c = 0; c < NCH; c++) {
        int st = c & 1;
        if (c < NCH - 1) {
            copyKV(c + 1, st ^ 1);
            CP_COMMIT;
            CP_WAIT1;
        } else {
            CP_WAIT0;
        }
        __syncthreads();

        float acc[12][4] = {};
#pragma unroll
        for (int s = 0; s < 2; s++) {
#pragma unroll
            for (int j = 0; j < 6; j++) {
                uint32_t kh_[4], kl_[4];
                LDSM_X4_T(kh_, sptr(sKp(st, 0, s * 16 + bkr) + j * 16 + bsel));
                LDSM_X4_T(kl_, sptr(sKp(st, 1, s * 16 + bkr) + j * 16 + bsel));
                mma16816(acc[2 * j],     qh[s], kh_[0], kh_[1]);
                mma16816(acc[2 * j],     qh[s], kl_[0], kl_[1]);
                mma16816(acc[2 * j],     ql[s], kh_[0], kh_[1]);
                mma16816(acc[2 * j + 1], qh[s], kh_[2], kh_[3]);
                mma16816(acc[2 * j + 1], qh[s], kl_[2], kl_[3]);
                mma16816(acc[2 * j + 1], ql[s], kh_[2], kh_[3]);
            }
        }
#pragma unroll
        for (int j = 0; j < 12; j++) {
            int key = c * CH + j * 8 + tid4 * 2;
            if (!smask[key])     { acc[j][0] = -1e9f; acc[j][2] = -1e9f; }
            if (!smask[key + 1]) { acc[j][1] = -1e9f; acc[j][3] = -1e9f; }
        }
        float mx0 = -INFINITY, mx1 = -INFINITY;
#pragma unroll
        for (int j = 0; j < 12; j++) {
            mx0 = fmaxf(mx0, fmaxf(acc[j][0], acc[j][1]));
            mx1 = fmaxf(mx1, fmaxf(acc[j][2], acc[j][3]));
        }
        mx0 = fmaxf(mx0, __shfl_xor_sync(0xFFFFFFFFu, mx0, 1));
        mx0 = fmaxf(mx0, __shfl_xor_sync(0xFFFFFFFFu, mx0, 2));
        mx1 = fmaxf(mx1, __shfl_xor_sync(0xFFFFFFFFu, mx1, 1));
        mx1 = fmaxf(mx1, __shfl_xor_sync(0xFFFFFFFFu, mx1, 2));
        float mn0 = fmaxf(m0r, mx0), mn1 = fmaxf(m1r, mx1);
        float rs0 = __expf(m0r - mn0), rs1 = __expf(m1r - mn1);
        float sum0 = 0.f, sum1 = 0.f;
#pragma unroll
        for (int j = 0; j < 12; j++) {
            acc[j][0] = __expf(acc[j][0] - mn0);
            acc[j][1] = __expf(acc[j][1] - mn0);
            acc[j][2] = __expf(acc[j][2] - mn1);
            acc[j][3] = __expf(acc[j][3] - mn1);
            sum0 += acc[j][0] + acc[j][1];
            sum1 += acc[j][2] + acc[j][3];
        }
        sum0 += __shfl_xor_sync(0xFFFFFFFFu, sum0, 1);
        sum0 += __shfl_xor_sync(0xFFFFFFFFu, sum0, 2);
        sum1 += __shfl_xor_sync(0xFFFFFFFFu, sum1, 1);
        sum1 += __shfl_xor_sync(0xFFFFFFFFu, sum1, 2);
        l0 = l0 * rs0 + sum0;
        l1 = l1 * rs1 + sum1;
#pragma unroll
        for (int dt = 0; dt < 4; dt++) {
            oacc[dt][0] *= rs0; oacc[dt][1] *= rs0;
            oacc[dt][2] *= rs1; oacc[dt][3] *= rs1;
        }
        m0r = mn0; m1r = mn1;

#pragma unroll
        for (int kt = 0; kt < 6; kt++) {
            uint32_t pha[4], pla[4];
            split2pack(acc[2 * kt][0],     acc[2 * kt][1],     pha[0], pla[0]);
            split2pack(acc[2 * kt][2],     acc[2 * kt][3],     pha[1], pla[1]);
            split2pack(acc[2 * kt + 1][0], acc[2 * kt + 1][1], pha[2], pla[2]);
            split2pack(acc[2 * kt + 1][2], acc[2 * kt + 1][3], pha[3], pla[3]);
#pragma unroll
            for (int dh2 = 0; dh2 < 2; dh2++) {
                uint32_t vh_[4], vl_[4];
                LDSM_X4_T(vh_, sptr(sVp(st, 0, kt * 16 + bkr) + dh2 * 16 + bsel));
                LDSM_X4_T(vl_, sptr(sVp(st, 1, kt * 16 + bkr) + dh2 * 16 + bsel));
                mma16816(oacc[dh2 * 2],     pha, vh_[0], vh_[1]);
                mma16816(oacc[dh2 * 2],     pha, vl_[0], vl_[1]);
                mma16816(oacc[dh2 * 2],     pla, vh_[0], vh_[1]);
                mma16816(oacc[dh2 * 2 + 1], pha, vh_[2], vh_[3]);
                mma16816(oacc[dh2 * 2 + 1], pha, vl_[2], vl_[3]);
                mma16816(oacc[dh2 * 2 + 1], pla, vh_[2], vh_[3]);
            }
        }
        __syncthreads();
    }

    float inv0 = 1.f / l0, inv1 = 1.f / l1;
    int qa = q0 + wid * 16 + g;
    int qb = qa + 8;
#pragma unroll
    for (int dt = 0; dt < 4; dt++) {
        int dim = h * 32 + dt * 8 + tid4 * 2;
        if (qa < GQ) {
            uint32_t hi, lo;
            split2pack(oacc[dt][0] * inv0, oacc[dt][1] * inv0, hi, lo);
            *(uint32_t*)&g_oaH[(size_t)(b * GQ + qa) * 256 + dim] = hi;
            *(uint32_t*)&g_oaL[(size_t)(b * GQ + qa) * 256 + dim] = lo;
        }
        if (qb < GQ) {
            uint32_t hi, lo;
            split2pack(oacc[dt][2] * inv1, oacc[dt][3] * inv1, hi, lo);
            *(uint32_t*)&g_oaH[(size_t)(b * GQ + qb) * 256 + dim] = hi;
            *(uint32_t*)&g_oaL[(size_t)(b * GQ + qb) * 256 + dim] = lo;
        }
    }
}

// ---------------- residual + LayerNorm (qin reconstructed from bf16 hi/lo) ----------------
__global__ void ln_k(const float* __restrict__ o2,
                     const float* __restrict__ g, const float* __restrict__ bb,
                     float* __restrict__ out) {
    __shared__ float red[256];
    __shared__ float mu_s, var_s;
    int r = blockIdx.x;
    int c = threadIdx.x;
    size_t idx = (size_t)r * 256 + c;
    float qv = __bfloat162float(g_qinH[idx]) + __bfloat162float(g_qinL[idx]);
    float h = qv + o2[idx];
    red[c] = h;
    __syncthreads();
    for (int o = 128; o > 0; o >>= 1) {
        if (c < o) red[c] += red[c + o];
        __syncthreads();
    }
    if (c == 0) mu_s = red[0] * (1.f / 256.f);
    __syncthreads();
    float d = h - mu_s;
    red[c] = d * d;
    __syncthreads();
    for (int o = 128; o > 0; o >>= 1) {
        if (c < o) red[c] += red[c + o];
        __syncthreads();
    }
    if (c == 0) var_s = red[0] * (1.f / 256.f);
    __syncthreads();
    out[idx] = d * rsqrtf(var_s + 1e-5f) * g[c] + bb[c];
}

__global__ void head_k(const float* __restrict__ feat, const float* __restrict__ Wseg,
                       const float* __restrict__ bseg, float* __restrict__ out) {
    __shared__ float Ws[256 * NOUT];
    int t = threadIdx.x;
    for (int i = t; i < 256 * NOUT; i += 256) Ws[i] = Wseg[i];
    __syncthreads();
    int p = blockIdx.x * 8 + (t >> 5);
    int lane = t & 31;
    int sg = g_segq[p];
    float v[8];
#pragma unroll
    for (int r = 0; r < 8; r++) {
        int c = lane + 32 * r;
        v[r] = feat[(size_t)p * 256 + c] + g_mhca[(size_t)sg * 256 + c];
    }
#pragma unroll
    for (int j = 0; j < NOUT; j++) {
        float s = 0.f;
#pragma unroll
        for (int r = 0; r < 8; r++) s = fmaf(v[r], Ws[(lane + 32 * r) * NOUT + j], s);
#pragma unroll
        for (int o = 16; o; o >>= 1) s += __shfl_xor_sync(0xFFFFFFFFu, s, o);
        if (lane == 0) out[(size_t)p * NOUT + j] = s + bseg[j];
    }
}

static void* sym_addr(const void* symbol) {
    void* p = nullptr;
    cudaGetSymbolAddress(&p, symbol);
    return p;
}

extern "C" void kernel_launch(void* const* d_in, const int* in_sizes, int n_in,
                              void* d_out, int out_size) {
    const float* feat  = (const float*)d_in[0];
    const float* Wpool = (const float*)d_in[1];
    const float* bpool = (const float*)d_in[2];
    const float* Wemb  = (const float*)d_in[3];
    const float* bemb  = (const float*)d_in[4];
    const float* Wq    = (const float*)d_in[5];
    const float* bq    = (const float*)d_in[6];
    const float* Wk    = (const float*)d_in[7];
    const float* bk    = (const float*)d_in[8];
    const float* Wv    = (const float*)d_in[9];
    const float* bv    = (const float*)d_in[10];
    const float* Wo    = (const float*)d_in[11];
    const float* bo    = (const float*)d_in[12];
    const float* lng   = (const float*)d_in[13];
    const float* lnb   = (const float*)d_in[14];
    const float* Wseg  = (const float*)d_in[15];
    const float* bseg  = (const float*)d_in[16];
    const int*   ind   = (const int*)d_in[17];
    float* out = (float*)d_out;

    unsigned* p_pool_key = (unsigned*)sym_addr(g_pool_key);
    unsigned long long* p_emb_key = (unsigned long long*)sym_addr(g_emb_key);
    int*      p_segq   = (int*)sym_addr(g_segq);
    int*      p_segk   = (int*)sym_addr(g_segk);
    int*      p_mask_q = (int*)sym_addr(g_mask_q);
    int*      p_mask_k = (int*)sym_addr(g_mask_k);
    float*    p_o2     = (float*)sym_addr(g_o2);
    float*    p_mhca   = (float*)sym_addr(g_mhca);
    __nv_bfloat16* p_featH = (__nv_bfloat16*)sym_addr(g_featH);
    __nv_bfloat16* p_featL = (__nv_bfloat16*)sym_addr(g_featL);
    __nv_bfloat16* p_wH    = (__nv_bfloat16*)sym_addr(g_wH);
    __nv_bfloat16* p_wL    = (__nv_bfloat16*)sym_addr(g_wL);
    __nv_bfloat16* p_oaH   = (__nv_bfloat16*)sym_addr(g_oaH);
    __nv_bfloat16* p_oaL   = (__nv_bfloat16*)sym_addr(g_oaL);

    cudaFuncSetAttribute(bf_gemm<10>, cudaFuncAttributeMaxDynamicSharedMemorySize, GEMM_SMEM);
    cudaFuncSetAttribute(bf_gemm<0>,  cudaFuncAttributeMaxDynamicSharedMemorySize, GEMM_SMEM);
    cudaFuncSetAttribute(qkvproj_k,   cudaFuncAttributeMaxDynamicSharedMemorySize, GEMM_SMEM);
    cudaFuncSetAttribute(fattn_k, cudaFuncAttributeMaxDynamicSharedMemorySize, FATTN_SMEM);

    const float qscale = 0.17677669529663687f;

    // 0. memsets
    cudaMemsetAsync(p_pool_key, 0, (size_t)SQ * DIM * 4);
    cudaMemsetAsync(p_emb_key, 0, (size_t)SK * DIM * 8);
    cudaMemsetAsync(p_mask_q, 0, SQ * 4);
    cudaMemsetAsync(p_mask_k, 0, SK * 4);
    // 1. splits + biases + PE table + prep (one launch)
    split_prep_k<<<FEAT_BLOCKS + W_BLOCKS + 1 + PREP_BLOCKS, 256>>>(
        feat, Wpool, Wemb, Wq, Wk, Wv, Wo, bq, bk, bv, ind);
    // 2. fused pool+emb GEMM (value scatter + packed argmax)
    bf_gemm<10><<<dim3(4, (NP + 127) / 128), 256, GEMM_SMEM>>>(
        p_featH, p_featL,
        p_wH + 0 * 65536, p_wL + 0 * 65536, bpool,
        p_wH + 1 * 65536, p_wL + 1 * 65536, bemb,
        nullptr, p_pool_key, p_segq, p_emb_key, p_segk, NP);
    // 3. merged PE-grid build
    build_k<<<SQ + SK, 256>>>(ind);
    // 4. merged Q+K+V projections
    qkvproj_k<<<QBLKS + 36, 256, GEMM_SMEM>>>(qscale);
    // 5. fused flash attention (96-key chunks)
    fattn_k<<<dim3((GQ + 127) / 128, BATCH * NH), 256, FATTN_SMEM>>>(p_mask_k);
    // 6. output projection + residual + LN
    bf_gemm<0><<<dim3(2, (SQ + 127) / 128), 256, GEMM_SMEM>>>(
        p_oaH, p_oaL, p_wH + 5 * 65536, p_wL + 5 * 65536, bo,
        nullptr, nullptr, nullptr, p_o2, nullptr, nullptr, nullptr, nullptr, SQ);
    ln_k<<<SQ, 256>>>(p_o2, lng, lnb, p_mhca);
    // 7. gather + seg head
    head_k<<<NP / 8, 256>>>(feat, Wseg, bseg, out);
}

// round 15
// speedup vs baseline: 1.0237x; 1.0237x over previous
#include <cuda_runtime.h>
#include <cuda_bf16.h>
#include <math.h>
#include <stdint.h>

#define NP   120000
#define DIM  256
#define BATCH 2
#define NH   8
#define NOUT 20
#define ZD 60
#define YD 45
#define XD 4
#define GQ 10800
#define SQ 21600
#define ZE 12
#define YE 24
#define XE 2
#define GK 576
#define SK 1152
#define NF 42
#define PEC 252

__device__ unsigned g_pool_key[SQ * DIM];
__device__ unsigned long long g_emb_key[SK * DIM];
__device__ int      g_mask_q[SQ];
__device__ int      g_mask_k[SK];
__device__ int      g_segq[NP];
__device__ int      g_segk[NP];
__device__ float    g_o2[(size_t)SQ * DIM];
__device__ float    g_mhca[(size_t)SQ * DIM];
__device__ float    g_invt[64];
__device__ float    g_bq[DIM];
__device__ float    g_bk[DIM];
__device__ float    g_bv[DIM];
__device__ __nv_bfloat16 g_featH[(size_t)NP * DIM];
__device__ __nv_bfloat16 g_featL[(size_t)NP * DIM];
__device__ __nv_bfloat16 g_wH[6 * 65536];
__device__ __nv_bfloat16 g_wL[6 * 65536];
__device__ __nv_bfloat16 g_qinH[(size_t)SQ * DIM];
__device__ __nv_bfloat16 g_qinL[(size_t)SQ * DIM];
__device__ __nv_bfloat16 g_kvH[SK * DIM];
__device__ __nv_bfloat16 g_kvL[SK * DIM];
__device__ __nv_bfloat16 g_qpH[(size_t)SQ * DIM];
__device__ __nv_bfloat16 g_qpL[(size_t)SQ * DIM];
__device__ __nv_bfloat16 g_oaH[(size_t)SQ * DIM];
__device__ __nv_bfloat16 g_oaL[(size_t)SQ * DIM];
__device__ __nv_bfloat16 g_k16h[16 * 32 * 576];
__device__ __nv_bfloat16 g_k16l[16 * 32 * 576];
__device__ __nv_bfloat16 g_v16h[16 * 576 * 32];
__device__ __nv_bfloat16 g_v16l[16 * 576 * 32];

__device__ __forceinline__ unsigned fenc(float f) {
    unsigned u = __float_as_uint(f);
    return (u & 0x80000000u) ? ~u : (u | 0x80000000u);
}
__device__ __forceinline__ float fdec(unsigned k) {
    return __uint_as_float((k & 0x80000000u) ? (k ^ 0x80000000u) : ~k);
}

__device__ __forceinline__ uint32_t sptr(const void* p) {
    return (uint32_t)__cvta_generic_to_shared(p);
}

#define LDSM_X4(r, addr) \
    asm volatile("ldmatrix.sync.aligned.m8n8.x4.shared.b16 {%0,%1,%2,%3}, [%4];" \
        : "=r"((r)[0]), "=r"((r)[1]), "=r"((r)[2]), "=r"((r)[3]) : "r"(addr))

#define LDSM_X4_T(r, addr) \
    asm volatile("ldmatrix.sync.aligned.m8n8.x4.trans.shared.b16 {%0,%1,%2,%3}, [%4];" \
        : "=r"((r)[0]), "=r"((r)[1]), "=r"((r)[2]), "=r"((r)[3]) : "r"(addr))

__device__ __forceinline__ void mma16816(float* c, const uint32_t* a, uint32_t b0, uint32_t b1) {
    asm volatile(
        "mma.sync.aligned.m16n8k16.row.col.f32.bf16.bf16.f32 "
        "{%0,%1,%2,%3}, {%4,%5,%6,%7}, {%8,%9}, {%0,%1,%2,%3};"
        : "+f"(c[0]), "+f"(c[1]), "+f"(c[2]), "+f"(c[3])
        : "r"(a[0]), "r"(a[1]), "r"(a[2]), "r"(a[3]), "r"(b0), "r"(b1));
}

#define CP16(dst, src) \
    asm volatile("cp.async.cg.shared.global [%0], [%1], 16;\n" :: "r"(dst), "l"(src))
#define CP_COMMIT asm volatile("cp.async.commit_group;\n" ::: "memory")
#define CP_WAIT2 asm volatile("cp.async.wait_group 2;\n" ::: "memory")
#define CP_WAIT1 asm volatile("cp.async.wait_group 1;\n" ::: "memory")
#define CP_WAIT0 asm volatile("cp.async.wait_group 0;\n" ::: "memory")

__device__ __forceinline__ void split_bf16(float v, __nv_bfloat16& h, __nv_bfloat16& l) {
    h = __float2bfloat16(v);
    l = __float2bfloat16(v - __bfloat162float(h));
}

__device__ __forceinline__ void split2pack(float a, float b, uint32_t& hi, uint32_t& lo) {
    __nv_bfloat16 ha = __float2bfloat16(a), hb = __float2bfloat16(b);
    __nv_bfloat16 la = __float2bfloat16(a - __bfloat162float(ha));
    __nv_bfloat16 lb = __float2bfloat16(b - __bfloat162float(hb));
    __nv_bfloat162 th(ha, hb), tl(la, lb);
    hi = *(uint32_t*)&th;
    lo = *(uint32_t*)&tl;
}

// ---------------- merged split + prep kernel ----------------
#define FEAT_BLOCKS 30000
#define W_BLOCKS 384
#define PREP_BLOCKS 469
__global__ void split_prep_k(const float* __restrict__ feat,
                             const float* __restrict__ w0, const float* __restrict__ w1,
                             const float* __restrict__ w2, const float* __restrict__ w3,
                             const float* __restrict__ w4, const float* __restrict__ w5,
                             const float* __restrict__ bq, const float* __restrict__ bk,
                             const float* __restrict__ bv, const int* __restrict__ ind) {
    int bx = blockIdx.x;
    int t = threadIdx.x;
    if (bx < FEAT_BLOCKS) {
        size_t i = (size_t)bx * 256 + t;
        float4 v = ((const float4*)feat)[i];
        __nv_bfloat16 hx, lx, hy, ly, hz, lz, hw, lw;
        split_bf16(v.x, hx, lx); split_bf16(v.y, hy, ly);
        split_bf16(v.z, hz, lz); split_bf16(v.w, hw, lw);
        ((__nv_bfloat162*)g_featH)[i * 2]     = __nv_bfloat162(hx, hy);
        ((__nv_bfloat162*)g_featH)[i * 2 + 1] = __nv_bfloat162(hz, hw);
        ((__nv_bfloat162*)g_featL)[i * 2]     = __nv_bfloat162(lx, ly);
        ((__nv_bfloat162*)g_featL)[i * 2 + 1] = __nv_bfloat162(lz, lw);
    } else if (bx < FEAT_BLOCKS + W_BLOCKS) {
        int i = (bx - FEAT_BLOCKS) * 256 + t;
        int which = i >> 14;
        int off = i & 16383;
        const float* src = which == 0 ? w0 : which == 1 ? w1 : which == 2 ? w2
                         : which == 3 ? w3 : which == 4 ? w4 : w5;
        float4 v = ((const float4*)src)[off];
        __nv_bfloat16 hx, lx, hy, ly, hz, lz, hw, lw;
        split_bf16(v.x, hx, lx); split_bf16(v.y, hy, ly);
        split_bf16(v.z, hz, lz); split_bf16(v.w, hw, lw);
        ((__nv_bfloat162*)g_wH)[i * 2]     = __nv_bfloat162(hx, hy);
        ((__nv_bfloat162*)g_wH)[i * 2 + 1] = __nv_bfloat162(hz, hw);
        ((__nv_bfloat162*)g_wL)[i * 2]     = __nv_bfloat162(lx, ly);
        ((__nv_bfloat162*)g_wL)[i * 2 + 1] = __nv_bfloat162(lz, lw);
    } else if (bx == FEAT_BLOCKS + W_BLOCKS) {
        if (t < NF) g_invt[t] = 1.0f / powf(10000.0f, (float)t / (float)NF);
        g_bq[t] = bq[t];
        g_bk[t] = bk[t];
        g_bv[t] = bv[t];
    } else {
        int i = (bx - FEAT_BLOCKS - W_BLOCKS - 1) * 256 + t;
        if (i >= NP) return;
        int b = ind[i * 4 + 0];
        int z = ind[i * 4 + 1];
        int y = ind[i * 4 + 2];
        int x = ind[i * 4 + 3];
        int sq = ((b * ZD + z / 8) * YD + y / 8) * XD + x / 8;
        int sk = ((b * ZE + z / 40) * YE + y / 15) * XE + x / 16;
        g_segq[i] = sq;
        g_segk[i] = sk;
        g_mask_q[sq] = 1;
        g_mask_k[sk] = 1;
    }
}

// ================= 3-stage pipelined bf16x3 MMA GEMM core =====================
#define AP 40
#define BP 136
#define SA3_BYTES (3 * 2 * 128 * AP * 2)
#define SB3_BYTES (3 * 2 * 32 * BP * 2)
#define GEMM_SMEM (SA3_BYTES + SB3_BYTES)

__device__ __forceinline__ __nv_bfloat16* pA(__nv_bfloat16* b, int st, int mat, int r) {
    return b + ((st * 2 + mat) * 128 + r) * AP;
}
__device__ __forceinline__ __nv_bfloat16* pB(__nv_bfloat16* b, int st, int mat, int r) {
    return b + ((st * 2 + mat) * 32 + r) * BP;
}

__device__ __forceinline__ void gemm_core(char* dsm, int t,
                                          const __nv_bfloat16* __restrict__ Ah,
                                          const __nv_bfloat16* __restrict__ Al,
                                          const __nv_bfloat16* __restrict__ Whp,
                                          const __nv_bfloat16* __restrict__ Wlp,
                                          int m0, int c0, int M, float acc[4][4][4]) {
    __nv_bfloat16* sA = (__nv_bfloat16*)dsm;
    __nv_bfloat16* sB = (__nv_bfloat16*)(dsm + SA3_BYTES);
    int wid = t >> 5, lane = t & 31;
    int wm = wid >> 2, wn = wid & 3;

    auto copyA = [&](int st, int ch) {
        int k0 = ch * 32;
#pragma unroll
        for (int i = 0; i < 2; i++) {
            int op = t * 2 + i;
            int r = op >> 2, seg = op & 3;
            int rowc = m0 + r;
            if (rowc >= M) rowc = M - 1;
            size_t src = (size_t)rowc * 256 + k0 + seg * 8;
            CP16(sptr(pA(sA, st, 0, r) + seg * 8), Ah + src);
            CP16(sptr(pA(sA, st, 1, r) + seg * 8), Al + src);
        }
    };
    auto copyB = [&](int st, int ch) {
        int k0 = ch * 32;
        int r = t >> 3;
#pragma unroll
        for (int q = 0; q < 2; q++) {
            int seg = (t & 7) + q * 8;
            size_t src = (size_t)(k0 + r) * 256 + c0 + seg * 8;
            CP16(sptr(pB(sB, st, 0, r) + seg * 8), Whp + src);
            CP16(sptr(pB(sB, st, 1, r) + seg * 8), Wlp + src);
        }
    };

    copyA(0, 0); copyB(0, 0); CP_COMMIT;
    copyA(1, 1); copyB(1, 1); CP_COMMIT;

    for (int ch = 0; ch < 8; ch++) {
        if (ch < 6) {
            int st2 = (ch + 2) % 3;
            copyA(st2, ch + 2);
            copyB(st2, ch + 2);
            CP_COMMIT;
            CP_WAIT2;
        } else if (ch == 6) {
            CP_WAIT1;
        } else {
            CP_WAIT0;
        }
        __syncthreads();
        int st = ch % 3;
#pragma unroll
        for (int ks = 0; ks < 2; ks++) {
            int arow = wm * 64 + (lane & 15);
            int akc = ks * 16 + ((lane & 16) ? 8 : 0);
            int bkr = ks * 16 + (lane & 15);
            int bnc = wn * 32 + ((lane & 16) ? 8 : 0);

            uint32_t af[4][4], bh[8], bl[8];
#pragma unroll
            for (int mt = 0; mt < 4; mt++)
                LDSM_X4(af[mt], sptr(pA(sA, st, 0, arow + mt * 16) + akc));
            LDSM_X4_T(bh,     sptr(pB(sB, st, 0, bkr) + bnc));
            LDSM_X4_T(bh + 4, sptr(pB(sB, st, 0, bkr) + bnc + 16));
            LDSM_X4_T(bl,     sptr(pB(sB, st, 1, bkr) + bnc));
            LDSM_X4_T(bl + 4, sptr(pB(sB, st, 1, bkr) + bnc + 16));

#pragma unroll
            for (int mt = 0; mt < 4; mt++) {
#pragma unroll
                for (int nt = 0; nt < 4; nt++) {
                    mma16816(acc[mt][nt], af[mt], bh[nt * 2], bh[nt * 2 + 1]);
                    mma16816(acc[mt][nt], af[mt], bl[nt * 2], bl[nt * 2 + 1]);
                }
            }
#pragma unroll
            for (int mt = 0; mt < 4; mt++)
                LDSM_X4(af[mt], sptr(pA(sA, st, 1, arow + mt * 16) + akc));
#pragma unroll
            for (int mt = 0; mt < 4; mt++) {
#pragma unroll
                for (int nt = 0; nt < 4; nt++)
                    mma16816(acc[mt][nt], af[mt], bh[nt * 2], bh[nt * 2 + 1]);
            }
        }
        __syncthreads();
    }
}

// MODE 10: fused pool/emb; MODE 0: fp32 store.
template <int MODE>
__global__ __launch_bounds__(256, 2) void bf_gemm(
    const __nv_bfloat16* __restrict__ Ah, const __nv_bfloat16* __restrict__ Al,
    const __nv_bfloat16* __restrict__ WhA, const __nv_bfloat16* __restrict__ WlA,
    const float* __restrict__ biasA,
    const __nv_bfloat16* __restrict__ WhB, const __nv_bfloat16* __restrict__ WlB,
    const float* __restrict__ biasB,
    float* __restrict__ Cout,
    unsigned* __restrict__ keyP, const int* __restrict__ segP,
    unsigned long long* __restrict__ keyE, const int* __restrict__ segE,
    int M)
{
    extern __shared__ char dsm[];
    int t = threadIdx.x, wid = t >> 5, lane = t & 31;
    int wm = wid >> 2, wn = wid & 3;
    int m0 = blockIdx.y * 128;

    bool isPool = false;
    const __nv_bfloat16 *Whp = WhA, *Wlp = WlA;
    const float* bp = biasA;
    int c0;
    if (MODE == 10) {
        isPool = ((blockIdx.x >> 1) == 0);
        if (!isPool) { Whp = WhB; Wlp = WlB; bp = biasB; }
        c0 = (blockIdx.x & 1) * 128;
    } else {
        c0 = blockIdx.x * 128;
    }

    float acc[4][4][4] = {};
    gemm_core(dsm, t, Ah, Al, Whp, Wlp, m0, c0, M, acc);

    int g = lane >> 2, tid4 = lane & 3;
#pragma unroll
    for (int mt = 0; mt < 4; mt++) {
#pragma unroll
        for (int nt = 0; nt < 4; nt++) {
            int coln = c0 + wn * 32 + nt * 8 + tid4 * 2;
            float b0 = bp[coln], b1 = bp[coln + 1];
#pragma unroll
            for (int half = 0; half < 2; half++) {
                int m = m0 + wm * 64 + mt * 16 + g + half * 8;
                if (m >= M) continue;
                float v0 = acc[mt][nt][half * 2 + 0] + b0;
                float v1 = acc[mt][nt][half * 2 + 1] + b1;
                if (MODE == 0) {
                    Cout[(size_t)m * 256 + coln]     = v0;
                    Cout[(size_t)m * 256 + coln + 1] = v1;
                } else {
                    if (isPool) {
                        int sg = segP[m];
                        atomicMax(&keyP[sg * 256 + coln],     fenc(v0));
                        atomicMax(&keyP[sg * 256 + coln + 1], fenc(v1));
                    } else {
                        int sg = segE[m];
                        unsigned long long p0 = ((unsigned long long)fenc(v0) << 32) | (unsigned)m;
                        unsigned long long p1 = ((unsigned long long)fenc(v1) << 32) | (unsigned)m;
                        atomicMax(&keyE[sg * 256 + coln],     p0);
                        atomicMax(&keyE[sg * 256 + coln + 1], p1);
                    }
                }
            }
        }
    }
}

// ---------------- merged Q+K+V projection (one launch) ----------------
#define QBLKS 338
__global__ __launch_bounds__(256, 2) void qkvproj_k(float qscale) {
    extern __shared__ char dsm[];
    int t = threadIdx.x, wid = t >> 5, lane = t & 31;
    int wm = wid >> 2, wn = wid & 3;
    int bx = blockIdx.x;

    const __nv_bfloat16 *Ahp, *Alp, *Whp, *Wlp;
    const float* bp;
    int m0, c0, M, mode;
    if (bx < QBLKS) {
        mode = 0;
        m0 = (bx >> 1) * 128;
        c0 = (bx & 1) * 128;
        Ahp = g_qinH; Alp = g_qinL;
        Whp = g_wH + 2 * 65536; Wlp = g_wL + 2 * 65536;
        bp = g_bq;
        M = SQ;
    } else {
        int r = bx - QBLKS;
        int sub = r & 3;
        int isV = sub >> 1;
        mode = 1 + isV;
        m0 = (r >> 2) * 128;
        c0 = (sub & 1) * 128;
        Ahp = g_kvH; Alp = g_kvL;
        Whp = g_wH + (3 + isV) * 65536;
        Wlp = g_wL + (3 + isV) * 65536;
        bp = isV ? g_bv : g_bk;
        M = SK;
    }

    float acc[4][4][4] = {};
    gemm_core(dsm, t, Ahp, Alp, Whp, Wlp, m0, c0, M, acc);

    int g = lane >> 2, tid4 = lane & 3;
#pragma unroll
    for (int mt = 0; mt < 4; mt++) {
#pragma unroll
        for (int nt = 0; nt < 4; nt++) {
            int coln = c0 + wn * 32 + nt * 8 + tid4 * 2;
            float b0 = bp[coln], b1 = bp[coln + 1];
#pragma unroll
            for (int half = 0; half < 2; half++) {
                int m = m0 + wm * 64 + mt * 16 + g + half * 8;
                if (m >= M) continue;
                float v0 = acc[mt][nt][half * 2 + 0] + b0;
                float v1 = acc[mt][nt][half * 2 + 1] + b1;
                if (mode == 0) {
                    uint32_t hi, lo;
                    split2pack(v0 * qscale, v1 * qscale, hi, lo);
                    *(uint32_t*)&g_qpH[(size_t)m * 256 + coln] = hi;
                    *(uint32_t*)&g_qpL[(size_t)m * 256 + coln] = lo;
                } else if (mode == 1) {
                    int b_ = m / 576, key = m - b_ * 576;
                    int hh = coln >> 5, d = coln & 31;
                    __nv_bfloat16 H, L;
                    split_bf16(v0, H, L);
                    size_t dst0 = (size_t)((b_ * 8 + hh) * 32 + d) * 576 + key;
                    g_k16h[dst0] = H; g_k16l[dst0] = L;
                    split_bf16(v1, H, L);
                    g_k16h[dst0 + 576] = H; g_k16l[dst0 + 576] = L;
                } else {
                    int b_ = m / 576, key = m - b_ * 576;
                    int hh = coln >> 5, d = coln & 31;
                    __nv_bfloat16 H, L;
                    size_t dst0 = ((size_t)(b_ * 8 + hh) * 576 + key) * 32 + d;
                    split_bf16(v0, H, L);
                    g_v16h[dst0] = H; g_v16l[dst0] = L;
                    split_bf16(v1, H, L);
                    g_v16h[dst0 + 1] = H; g_v16l[dst0 + 1] = L;
                }
            }
        }
    }
}

// ---------------- sine PE ----------------
__device__ __forceinline__ float pe_val(float cz, float cy, float cx, int c) {
    if (c >= PEC) return 0.f;
    int axis = c / (2 * NF);
    int r = c - axis * (2 * NF);
    int j = r < NF ? r : r - NF;
    float coord = (axis == 0) ? cz : (axis == 1) ? cy : cx;
    float spd = (axis == 0) ? 480.f : (axis == 1) ? 360.f : 32.f;
    float ang = coord / spd * 6.283185307179586f * g_invt[j];
    return (r < NF) ? __sinf(ang) : __cosf(ang);
}

// ---------------- merged build: buildq [0,SQ) + (embc+buildkv) [SQ, SQ+SK) ----------------
__global__ void build_k(const int* __restrict__ ind) {
    int bx = blockIdx.x;
    int c = threadIdx.x;
    if (bx < SQ) {
        int s = bx;
        int rem = s % GQ;
        float cz = (float)((rem / (YD * XD)) * 8);
        float cy = (float)(((rem / XD) % YD) * 8);
        float cx = (float)((rem % XD) * 8);
        float base = g_mask_q[s] ? fdec(g_pool_key[(size_t)s * 256 + c]) : 0.f;
        float val = base + pe_val(cz, cy, cx, c);
        size_t idx = (size_t)s * 256 + c;
        __nv_bfloat16 h, l;
        split_bf16(val, h, l);
        g_qinH[idx] = h;
        g_qinL[idx] = l;
    } else {
        __shared__ float rz[256], ry[256], rx[256];
        int s = bx - SQ;
        unsigned long long key = g_emb_key[s * 256 + c];
        int i = (int)(key & 0xFFFFFFFFull);
        int z = ind[i * 4 + 1], y = ind[i * 4 + 2], x = ind[i * 4 + 3];
        rz[c] = (float)(z / 40);
        ry[c] = (float)(y / 15);
        rx[c] = (float)(x / 16);
        __syncthreads();
        for (int o = 128; o > 0; o >>= 1) {
            if (c < o) { rz[c] += rz[c + o]; ry[c] += ry[c + o]; rx[c] += rx[c + o]; }
            __syncthreads();
        }
        float cz = rz[0] * (1.f / 256.f) * 40.f;
        float cy = ry[0] * (1.f / 256.f) * 15.f;
        float cx = rx[0] * (1.f / 256.f) * 16.f;
        float base = g_mask_k[s] ? fdec((unsigned)(key >> 32)) : 0.f;
        float val = base + pe_val(cz, cy, cx, c);
        __nv_bfloat16 h, l;
        split_bf16(val, h, l);
        g_kvH[s * 256 + c] = h;
        g_kvL[s * 256 + c] = l;
    }
}

// ---------------- fused flash attention (64-key chunks, known-good R13 config) ----------------
#define QPAD 40
#define KPAD 72
#define FQ_BYTES (2 * 128 * QPAD * 2)
#define FK_BYTES (2 * 2 * 32 * KPAD * 2)
#define FV_BYTES (2 * 2 * 64 * QPAD * 2)
#define FATTN_SMEM (FQ_BYTES + FK_BYTES + FV_BYTES + GK * 4)

__global__ __launch_bounds__(256) void fattn_k(const int* __restrict__ maskk) {
    extern __shared__ char fsm[];
    __nv_bfloat16* sQ = (__nv_bfloat16*)fsm;
    __nv_bfloat16* sK = (__nv_bfloat16*)(fsm + FQ_BYTES);
    __nv_bfloat16* sV = (__nv_bfloat16*)(fsm + FQ_BYTES + FK_BYTES);
    int* smask = (int*)(fsm + FQ_BYTES + FK_BYTES + FV_BYTES);

    int t = threadIdx.x, wid = t >> 5, lane = t & 31;
    int bh = blockIdx.y, b = bh >> 3, h = bh & 7;
    int q0 = blockIdx.x * 128;

    auto sQp = [&](int hl, int r) { return sQ + (hl * 128 + r) * QPAD; };
    auto sKp = [&](int st, int hl, int d) { return sK + ((st * 2 + hl) * 32 + d) * KPAD; };
    auto sVp = [&](int st, int hl, int k) { return sV + ((st * 2 + hl) * 64 + k) * QPAD; };

    auto copyKV = [&](int c, int st) {
        int d = t >> 3, ks = (t & 7) * 8;
        size_t srck = (size_t)(bh * 32 + d) * 576 + c * 64 + ks;
        CP16(sptr(sKp(st, 0, d) + ks), g_k16h + srck);
        CP16(sptr(sKp(st, 1, d) + ks), g_k16l + srck);
        int key = t >> 2, ds = (t & 3) * 8;
        size_t srcv = (size_t)(bh * 576 + c * 64 + key) * 32 + ds;
        CP16(sptr(sVp(st, 0, key) + ds), g_v16h + srcv);
        CP16(sptr(sVp(st, 1, key) + ds), g_v16l + srcv);
    };

    copyKV(0, 0);
    CP_COMMIT;

    {
#pragma unroll
        for (int i = 0; i < 2; i++) {
            int op = t * 2 + i;
            int r = op >> 2, seg = op & 3;
            uint4 vh = make_uint4(0, 0, 0, 0), vl = vh;
            if (q0 + r < GQ) {
                size_t s = (size_t)(b * GQ + q0 + r) * 256 + h * 32 + seg * 8;
                vh = *(const uint4*)&g_qpH[s];
                vl = *(const uint4*)&g_qpL[s];
            }
            *(uint4*)(sQp(0, r) + seg * 8) = vh;
            *(uint4*)(sQp(1, r) + seg * 8) = vl;
        }
    }
    for (int i = t; i < GK; i += 256) smask[i] = maskk[b * GK + i];
    __syncthreads();

    uint32_t qh[2][4], ql[2][4];
    {
        int arow = wid * 16 + (lane & 15);
#pragma unroll
        for (int s = 0; s < 2; s++) {
            int akc = s * 16 + ((lane & 16) ? 8 : 0);
            LDSM_X4(qh[s], sptr(sQp(0, arow) + akc));
            LDSM_X4(ql[s], sptr(sQp(1, arow) + akc));
        }
    }

    float m0r = -INFINITY, m1r = -INFINITY, l0 = 0.f, l1 = 0.f;
    float oacc[4][4] = {};
    int g = lane >> 2, tid4 = lane & 3;
    int bkr = lane & 15;
    int bsel = (lane & 16) ? 8 : 0;

    for (int c = 0; c < 9; c++) {
        int st = c & 1;
        if (c < 8) {
            copyKV(c + 1, st ^ 1);
            CP_COMMIT;
            CP_WAIT1;
        } else {
            CP_WAIT0;
        }
        __syncthreads();

        float acc[8][4] = {};
#pragma unroll
        for (int s = 0; s < 2; s++) {
#pragma unroll
            for (int j = 0; j < 4; j++) {
                uint32_t kh_[4], kl_[4];
                LDSM_X4_T(kh_, sptr(sKp(st, 0, s * 16 + bkr) + j * 16 + bsel));
                LDSM_X4_T(kl_, sptr(sKp(st, 1, s * 16 + bkr) + j * 16 + bsel));
                mma16816(acc[2 * j],     qh[s], kh_[0], kh_[1]);
                mma16816(acc[2 * j],     qh[s], kl_[0], kl_[1]);
                mma16816(acc[2 * j],     ql[s], kh_[0], kh_[1]);
                mma16816(acc[2 * j + 1], qh[s], kh_[2], kh_[3]);
                mma16816(acc[2 * j + 1], qh[s], kl_[2], kl_[3]);
                mma16816(acc[2 * j + 1], ql[s], kh_[2], kh_[3]);
            }
        }
#pragma unroll
        for (int j = 0; j < 8; j++) {
            int key = c * 64 + j * 8 + tid4 * 2;
            if (!smask[key])     { acc[j][0] = -1e9f; acc[j][2] = -1e9f; }
            if (!smask[key + 1]) { acc[j][1] = -1e9f; acc[j][3] = -1e9f; }
        }
        float mx0 = -INFINITY, mx1 = -INFINITY;
#pragma unroll
        for (int j = 0; j < 8; j++) {
            mx0 = fmaxf(mx0, fmaxf(acc[j][0], acc[j][1]));
            mx1 = fmaxf(mx1, fmaxf(acc[j][2], acc[j][3]));
        }
        mx0 = fmaxf(mx0, __shfl_xor_sync(0xFFFFFFFFu, mx0, 1));
        mx0 = fmaxf(mx0, __shfl_xor_sync(0xFFFFFFFFu, mx0, 2));
        mx1 = fmaxf(mx1, __shfl_xor_sync(0xFFFFFFFFu, mx1, 1));
        mx1 = fmaxf(mx1, __shfl_xor_sync(0xFFFFFFFFu, mx1, 2));
        float mn0 = fmaxf(m0r, mx0), mn1 = fmaxf(m1r, mx1);
        float rs0 = __expf(m0r - mn0), rs1 = __expf(m1r - mn1);
        float sum0 = 0.f, sum1 = 0.f;
#pragma unroll
        for (int j = 0; j < 8; j++) {
            acc[j][0] = __expf(acc[j][0] - mn0);
            acc[j][1] = __expf(acc[j][1] - mn0);
            acc[j][2] = __expf(acc[j][2] - mn1);
            acc[j][3] = __expf(acc[j][3] - mn1);
            sum0 += acc[j][0] + acc[j][1];
            sum1 += acc[j][2] + acc[j][3];
        }
        sum0 += __shfl_xor_sync(0xFFFFFFFFu, sum0, 1);
        sum0 += __shfl_xor_sync(0xFFFFFFFFu, sum0, 2);
        sum1 += __shfl_xor_sync(0xFFFFFFFFu, sum1, 1);
        sum1 += __shfl_xor_sync(0xFFFFFFFFu, sum1, 2);
        l0 = l0 * rs0 + sum0;
        l1 = l1 * rs1 + sum1;
#pragma unroll
        for (int dt = 0; dt < 4; dt++) {
            oacc[dt][0] *= rs0; oacc[dt][1] *= rs0;
            oacc[dt][2] *= rs1; oacc[dt][3] *= rs1;
        }
        m0r = mn0; m1r = mn1;

#pragma unroll
        for (int kt = 0; kt < 4; kt++) {
            uint32_t pha[4], pla[4];
            split2pack(acc[2 * kt][0],     acc[2 * kt][1],     pha[0], pla[0]);
            split2pack(acc[2 * kt][2],     acc[2 * kt][3],     pha[1], pla[1]);
            split2pack(acc[2 * kt + 1][0], acc[2 * kt + 1][1], pha[2], pla[2]);
            split2pack(acc[2 * kt + 1][2], acc[2 * kt + 1][3], pha[3], pla[3]);
#pragma unroll
            for (int dh2 = 0; dh2 < 2; dh2++) {
                uint32_t vh_[4], vl_[4];
                LDSM_X4_T(vh_, sptr(sVp(st, 0, kt * 16 + bkr) + dh2 * 16 + bsel));
                LDSM_X4_T(vl_, sptr(sVp(st, 1, kt * 16 + bkr) + dh2 * 16 + bsel));
                mma16816(oacc[dh2 * 2],     pha, vh_[0], vh_[1]);
                mma16816(oacc[dh2 * 2],     pha, vl_[0], vl_[1]);
                mma16816(oacc[dh2 * 2],     pla, vh_[0], vh_[1]);
                mma16816(oacc[dh2 * 2 + 1], pha, vh_[2], vh_[3]);
                mma16816(oacc[dh2 * 2 + 1], pha, vl_[2], vl_[3]);
                mma16816(oacc[dh2 * 2 + 1], pla, vh_[2], vh_[3]);
            }
        }
        __syncthreads();
    }

    float inv0 = 1.f / l0, inv1 = 1.f / l1;
    int qa = q0 + wid * 16 + g;
    int qb = qa + 8;
#pragma unroll
    for (int dt = 0; dt < 4; dt++) {
        int dim = h * 32 + dt * 8 + tid4 * 2;
        if (qa < GQ) {
            uint32_t hi, lo;
            split2pack(oacc[dt][0] * inv0, oacc[dt][1] * inv0, hi, lo);
            *(uint32_t*)&g_oaH[(size_t)(b * GQ + qa) * 256 + dim] = hi;
            *(uint32_t*)&g_oaL[(size_t)(b * GQ + qa) * 256 + dim] = lo;
        }
        if (qb < GQ) {
            uint32_t hi, lo;
            split2pack(oacc[dt][2] * inv1, oacc[dt][3] * inv1, hi, lo);
            *(uint32_t*)&g_oaH[(size_t)(b * GQ + qb) * 256 + dim] = hi;
            *(uint32_t*)&g_oaL[(size_t)(b * GQ + qb) * 256 + dim] = lo;
        }
    }
}

// ---------------- residual + LayerNorm (qin reconstructed from bf16 hi/lo) ----------------
__global__ void ln_k(const float* __restrict__ o2,
                     const float* __restrict__ g, const float* __restrict__ bb,
                     float* __restrict__ out) {
    __shared__ float red[256];
    __shared__ float mu_s, var_s;
    int r = blockIdx.x;
    int c = threadIdx.x;
    size_t idx = (size_t)r * 256 + c;
    float qv = __bfloat162float(g_qinH[idx]) + __bfloat162float(g_qinL[idx]);
    float h = qv + o2[idx];
    red[c] = h;
    __syncthreads();
    for (int o = 128; o > 0; o >>= 1) {
        if (c < o) red[c] += red[c + o];
        __syncthreads();
    }
    if (c == 0) mu_s = red[0] * (1.f / 256.f);
    __syncthreads();
    float d = h - mu_s;
    red[c] = d * d;
    __syncthreads();
    for (int o = 128; o > 0; o >>= 1) {
        if (c < o) red[c] += red[c + o];
        __syncthreads();
    }
    if (c == 0) var_s = red[0] * (1.f / 256.f);
    __syncthreads();
    out[idx] = d * rsqrtf(var_s + 1e-5f) * g[c] + bb[c];
}

__global__ void head_k(const float* __restrict__ feat, const float* __restrict__ Wseg,
                       const float* __restrict__ bseg, float* __restrict__ out) {
    __shared__ float Ws[256 * NOUT];
    int t = threadIdx.x;
    for (int i = t; i < 256 * NOUT; i += 256) Ws[i] = Wseg[i];
    __syncthreads();
    int p = blockIdx.x * 8 + (t >> 5);
    int lane = t & 31;
    int sg = g_segq[p];
    float v[8];
#pragma unroll
    for (int r = 0; r < 8; r++) {
        int c = lane + 32 * r;
        v[r] = feat[(size_t)p * 256 + c] + g_mhca[(size_t)sg * 256 + c];
    }
#pragma unroll
    for (int j = 0; j < NOUT; j++) {
        float s = 0.f;
#pragma unroll
        for (int r = 0; r < 8; r++) s = fmaf(v[r], Ws[(lane + 32 * r) * NOUT + j], s);
#pragma unroll
        for (int o = 16; o; o >>= 1) s += __shfl_xor_sync(0xFFFFFFFFu, s, o);
        if (lane == 0) out[(size_t)p * NOUT + j] = s + bseg[j];
    }
}

static void* sym_addr(const void* symbol) {
    void* p = nullptr;
    cudaGetSymbolAddress(&p, symbol);
    return p;
}

extern "C" void kernel_launch(void* const* d_in, const int* in_sizes, int n_in,
                              void* d_out, int out_size) {
    const float* feat  = (const float*)d_in[0];
    const float* Wpool = (const float*)d_in[1];
    const float* bpool = (const float*)d_in[2];
    const float* Wemb  = (const float*)d_in[3];
    const float* bemb  = (const float*)d_in[4];
    const float* Wq    = (const float*)d_in[5];
    const float* bq    = (const float*)d_in[6];
    const float* Wk    = (const float*)d_in[7];
    const float* bk    = (const float*)d_in[8];
    const float* Wv    = (const float*)d_in[9];
    const float* bv    = (const float*)d_in[10];
    const float* Wo    = (const float*)d_in[11];
    const float* bo    = (const float*)d_in[12];
    const float* lng   = (const float*)d_in[13];
    const float* lnb   = (const float*)d_in[14];
    const float* Wseg  = (const float*)d_in[15];
    const float* bseg  = (const float*)d_in[16];
    const int*   ind   = (const int*)d_in[17];
    float* out = (float*)d_out;

    unsigned* p_pool_key = (unsigned*)sym_addr(g_pool_key);
    unsigned long long* p_emb_key = (unsigned long long*)sym_addr(g_emb_key);
    int*      p_segq   = (int*)sym_addr(g_segq);
    int*      p_segk   = (int*)sym_addr(g_segk);
    int*      p_mask_q = (int*)sym_addr(g_mask_q);
    int*      p_mask_k = (int*)sym_addr(g_mask_k);
    float*    p_o2     = (float*)sym_addr(g_o2);
    float*    p_mhca   = (float*)sym_addr(g_mhca);
    __nv_bfloat16* p_featH = (__nv_bfloat16*)sym_addr(g_featH);
    __nv_bfloat16* p_featL = (__nv_bfloat16*)sym_addr(g_featL);
    __nv_bfloat16* p_wH    = (__nv_bfloat16*)sym_addr(g_wH);
    __nv_bfloat16* p_wL    = (__nv_bfloat16*)sym_addr(g_wL);
    __nv_bfloat16* p_oaH   = (__nv_bfloat16*)sym_addr(g_oaH);
    __nv_bfloat16* p_oaL   = (__nv_bfloat16*)sym_addr(g_oaL);

    cudaFuncSetAttribute(bf_gemm<10>, cudaFuncAttributeMaxDynamicSharedMemorySize, GEMM_SMEM);
    cudaFuncSetAttribute(bf_gemm<0>,  cudaFuncAttributeMaxDynamicSharedMemorySize, GEMM_SMEM);
    cudaFuncSetAttribute(qkvproj_k,   cudaFuncAttributeMaxDynamicSharedMemorySize, GEMM_SMEM);
    cudaFuncSetAttribute(fattn_k, cudaFuncAttributeMaxDynamicSharedMemorySize, FATTN_SMEM);

    const float qscale = 0.17677669529663687f;

    // 0. memsets
    cudaMemsetAsync(p_pool_key, 0, (size_t)SQ * DIM * 4);
    cudaMemsetAsync(p_emb_key, 0, (size_t)SK * DIM * 8);
    cudaMemsetAsync(p_mask_q, 0, SQ * 4);
    cudaMemsetAsync(p_mask_k, 0, SK * 4);
    // 1. splits + biases + PE table + prep (one launch)
    split_prep_k<<<FEAT_BLOCKS + W_BLOCKS + 1 + PREP_BLOCKS, 256>>>(
        feat, Wpool, Wemb, Wq, Wk, Wv, Wo, bq, bk, bv, ind);
    // 2. fused pool+emb GEMM (value scatter + packed argmax)
    bf_gemm<10><<<dim3(4, (NP + 127) / 128), 256, GEMM_SMEM>>>(
        p_featH, p_featL,
        p_wH + 0 * 65536, p_wL + 0 * 65536, bpool,
        p_wH + 1 * 65536, p_wL + 1 * 65536, bemb,
        nullptr, p_pool_key, p_segq, p_emb_key, p_segk, NP);
    // 3. merged PE-grid build
    build_k<<<SQ + SK, 256>>>(ind);
    // 4. merged Q+K+V projections
    qkvproj_k<<<QBLKS + 36, 256, GEMM_SMEM>>>(qscale);
    // 5. fused flash attention (64-key chunks)
    fattn_k<<<dim3((GQ + 127) / 128, BATCH * NH), 256, FATTN_SMEM>>>(p_mask_k);
    // 6. output projection + residual + LN
    bf_gemm<0><<<dim3(2, (SQ + 127) / 128), 256, GEMM_SMEM>>>(
        p_oaH, p_oaL, p_wH + 5 * 65536, p_wL + 5 * 65536, bo,
        nullptr, nullptr, nullptr, p_o2, nullptr, nullptr, nullptr, nullptr, SQ);
    ln_k<<<SQ, 256>>>(p_o2, lng, lnb, p_mhca);
    // 7. gather + seg head
    head_k<<<NP / 8, 256>>>(feat, Wseg, bseg, out);
}

// round 16
// speedup vs baseline: 1.0340x; 1.0101x over previous
#include <cuda_runtime.h>
#include <cuda_bf16.h>
#include <math.h>
#include <stdint.h>

#define NP   120000
#define DIM  256
#define BATCH 2
#define NH   8
#define NOUT 20
#define ZD 60
#define YD 45
#define XD 4
#define GQ 10800
#define SQ 21600
#define ZE 12
#define YE 24
#define XE 2
#define GK 576
#define SK 1152
#define NF 42
#define PEC 252

__device__ unsigned g_pool_key[SQ * DIM];
__device__ unsigned long long g_emb_key[SK * DIM];
__device__ int      g_mask_q[SQ];
__device__ int      g_mask_k[SK];
__device__ int      g_segq[NP];
__device__ int      g_segk[NP];
__device__ float    g_o2[(size_t)SQ * DIM];
__device__ float    g_mhca[(size_t)SQ * DIM];
__device__ float    g_invt[64];
__device__ float    g_bq[DIM];
__device__ float    g_bk[DIM];
__device__ float    g_bv[DIM];
__device__ __nv_bfloat16 g_featH[(size_t)NP * DIM];
__device__ __nv_bfloat16 g_featL[(size_t)NP * DIM];
__device__ __nv_bfloat16 g_wH[6 * 65536];
__device__ __nv_bfloat16 g_wL[6 * 65536];
__device__ __nv_bfloat16 g_qinH[(size_t)SQ * DIM];
__device__ __nv_bfloat16 g_qinL[(size_t)SQ * DIM];
__device__ __nv_bfloat16 g_kvH[SK * DIM];
__device__ __nv_bfloat16 g_kvL[SK * DIM];
__device__ __nv_bfloat16 g_qpH[(size_t)SQ * DIM];
__device__ __nv_bfloat16 g_qpL[(size_t)SQ * DIM];
__device__ __nv_bfloat16 g_oaH[(size_t)SQ * DIM];
__device__ __nv_bfloat16 g_oaL[(size_t)SQ * DIM];
__device__ __nv_bfloat16 g_k16h[16 * 32 * 576];
__device__ __nv_bfloat16 g_k16l[16 * 32 * 576];
__device__ __nv_bfloat16 g_v16h[16 * 576 * 32];
__device__ __nv_bfloat16 g_v16l[16 * 576 * 32];

__device__ __forceinline__ unsigned fenc(float f) {
    unsigned u = __float_as_uint(f);
    return (u & 0x80000000u) ? ~u : (u | 0x80000000u);
}
__device__ __forceinline__ float fdec(unsigned k) {
    return __uint_as_float((k & 0x80000000u) ? (k ^ 0x80000000u) : ~k);
}

__device__ __forceinline__ uint32_t sptr(const void* p) {
    return (uint32_t)__cvta_generic_to_shared(p);
}

#define LDSM_X4(r, addr) \
    asm volatile("ldmatrix.sync.aligned.m8n8.x4.shared.b16 {%0,%1,%2,%3}, [%4];" \
        : "=r"((r)[0]), "=r"((r)[1]), "=r"((r)[2]), "=r"((r)[3]) : "r"(addr))

#define LDSM_X4_T(r, addr) \
    asm volatile("ldmatrix.sync.aligned.m8n8.x4.trans.shared.b16 {%0,%1,%2,%3}, [%4];" \
        : "=r"((r)[0]), "=r"((r)[1]), "=r"((r)[2]), "=r"((r)[3]) : "r"(addr))

__device__ __forceinline__ void mma16816(float* c, const uint32_t* a, uint32_t b0, uint32_t b1) {
    asm volatile(
        "mma.sync.aligned.m16n8k16.row.col.f32.bf16.bf16.f32 "
        "{%0,%1,%2,%3}, {%4,%5,%6,%7}, {%8,%9}, {%0,%1,%2,%3};"
        : "+f"(c[0]), "+f"(c[1]), "+f"(c[2]), "+f"(c[3])
        : "r"(a[0]), "r"(a[1]), "r"(a[2]), "r"(a[3]), "r"(b0), "r"(b1));
}

#define CP16(dst, src) \
    asm volatile("cp.async.cg.shared.global [%0], [%1], 16;\n" :: "r"(dst), "l"(src))
#define CP_COMMIT asm volatile("cp.async.commit_group;\n" ::: "memory")
#define CP_WAIT1 asm volatile("cp.async.wait_group 1;\n" ::: "memory")
#define CP_WAIT0 asm volatile("cp.async.wait_group 0;\n" ::: "memory")

__device__ __forceinline__ void split_bf16(float v, __nv_bfloat16& h, __nv_bfloat16& l) {
    h = __float2bfloat16(v);
    l = __float2bfloat16(v - __bfloat162float(h));
}

// fast packed split: identical RN rounding, fewer instructions
__device__ __forceinline__ void split2pack(float a, float b, uint32_t& hi, uint32_t& lo) {
    uint32_t h;
    asm("cvt.rn.bf16x2.f32 %0, %1, %2;" : "=r"(h) : "f"(b), "f"(a));  // upper=bf16(b), lower=bf16(a)
    float ha = __uint_as_float(h << 16);
    float hb = __uint_as_float(h & 0xFFFF0000u);
    float la = a - ha;
    float lb = b - hb;
    uint32_t l;
    asm("cvt.rn.bf16x2.f32 %0, %1, %2;" : "=r"(l) : "f"(lb), "f"(la));
    hi = h;
    lo = l;
}

// ---------------- merged split + prep kernel ----------------
#define FEAT_BLOCKS 30000
#define W_BLOCKS 384
#define PREP_BLOCKS 469
__global__ void split_prep_k(const float* __restrict__ feat,
                             const float* __restrict__ w0, const float* __restrict__ w1,
                             const float* __restrict__ w2, const float* __restrict__ w3,
                             const float* __restrict__ w4, const float* __restrict__ w5,
                             const float* __restrict__ bq, const float* __restrict__ bk,
                             const float* __restrict__ bv, const int* __restrict__ ind) {
    int bx = blockIdx.x;
    int t = threadIdx.x;
    if (bx < FEAT_BLOCKS) {
        size_t i = (size_t)bx * 256 + t;
        float4 v = ((const float4*)feat)[i];
        uint32_t h0, l0, h1, l1;
        split2pack(v.x, v.y, h0, l0);
        split2pack(v.z, v.w, h1, l1);
        ((uint32_t*)g_featH)[i * 2]     = h0;
        ((uint32_t*)g_featH)[i * 2 + 1] = h1;
        ((uint32_t*)g_featL)[i * 2]     = l0;
        ((uint32_t*)g_featL)[i * 2 + 1] = l1;
    } else if (bx < FEAT_BLOCKS + W_BLOCKS) {
        int i = (bx - FEAT_BLOCKS) * 256 + t;
        int which = i >> 14;
        int off = i & 16383;
        const float* src = which == 0 ? w0 : which == 1 ? w1 : which == 2 ? w2
                         : which == 3 ? w3 : which == 4 ? w4 : w5;
        float4 v = ((const float4*)src)[off];
        uint32_t h0, l0, h1, l1;
        split2pack(v.x, v.y, h0, l0);
        split2pack(v.z, v.w, h1, l1);
        ((uint32_t*)g_wH)[i * 2]     = h0;
        ((uint32_t*)g_wH)[i * 2 + 1] = h1;
        ((uint32_t*)g_wL)[i * 2]     = l0;
        ((uint32_t*)g_wL)[i * 2 + 1] = l1;
    } else if (bx == FEAT_BLOCKS + W_BLOCKS) {
        if (t < NF) g_invt[t] = 1.0f / powf(10000.0f, (float)t / (float)NF);
        g_bq[t] = bq[t];
        g_bk[t] = bk[t];
        g_bv[t] = bv[t];
    } else {
        int i = (bx - FEAT_BLOCKS - W_BLOCKS - 1) * 256 + t;
        if (i >= NP) return;
        int b = ind[i * 4 + 0];
        int z = ind[i * 4 + 1];
        int y = ind[i * 4 + 2];
        int x = ind[i * 4 + 3];
        int sq = ((b * ZD + z / 8) * YD + y / 8) * XD + x / 8;
        int sk = ((b * ZE + z / 40) * YE + y / 15) * XE + x / 16;
        g_segq[i] = sq;
        g_segk[i] = sk;
        g_mask_q[sq] = 1;
        g_mask_k[sk] = 1;
    }
}

// ================= 3-stage pipelined bf16x3 MMA GEMM core (1 barrier/chunk) =========
#define AP 40
#define BP 136
#define SA3_BYTES (3 * 2 * 128 * AP * 2)
#define SB3_BYTES (3 * 2 * 32 * BP * 2)
#define GEMM_SMEM (SA3_BYTES + SB3_BYTES)

__device__ __forceinline__ __nv_bfloat16* pA(__nv_bfloat16* b, int st, int mat, int r) {
    return b + ((st * 2 + mat) * 128 + r) * AP;
}
__device__ __forceinline__ __nv_bfloat16* pB(__nv_bfloat16* b, int st, int mat, int r) {
    return b + ((st * 2 + mat) * 32 + r) * BP;
}

__device__ __forceinline__ void gemm_core(char* dsm, int t,
                                          const __nv_bfloat16* __restrict__ Ah,
                                          const __nv_bfloat16* __restrict__ Al,
                                          const __nv_bfloat16* __restrict__ Whp,
                                          const __nv_bfloat16* __restrict__ Wlp,
                                          int m0, int c0, int M, float acc[4][4][4]) {
    __nv_bfloat16* sA = (__nv_bfloat16*)dsm;
    __nv_bfloat16* sB = (__nv_bfloat16*)(dsm + SA3_BYTES);
    int wid = t >> 5, lane = t & 31;
    int wm = wid >> 2, wn = wid & 3;

    auto copyA = [&](int st, int ch) {
        int k0 = ch * 32;
#pragma unroll
        for (int i = 0; i < 2; i++) {
            int op = t * 2 + i;
            int r = op >> 2, seg = op & 3;
            int rowc = m0 + r;
            if (rowc >= M) rowc = M - 1;
            size_t src = (size_t)rowc * 256 + k0 + seg * 8;
            CP16(sptr(pA(sA, st, 0, r) + seg * 8), Ah + src);
            CP16(sptr(pA(sA, st, 1, r) + seg * 8), Al + src);
        }
    };
    auto copyB = [&](int st, int ch) {
        int k0 = ch * 32;
        int r = t >> 3;
#pragma unroll
        for (int q = 0; q < 2; q++) {
            int seg = (t & 7) + q * 8;
            size_t src = (size_t)(k0 + r) * 256 + c0 + seg * 8;
            CP16(sptr(pB(sB, st, 0, r) + seg * 8), Whp + src);
            CP16(sptr(pB(sB, st, 1, r) + seg * 8), Wlp + src);
        }
    };

    copyA(0, 0); copyB(0, 0); CP_COMMIT;
    copyA(1, 1); copyB(1, 1); CP_COMMIT;

    for (int ch = 0; ch < 8; ch++) {
        // wait for group ch (leaves at most group ch+1 pending)
        if (ch < 7) { CP_WAIT1; } else { CP_WAIT0; }
        __syncthreads();   // all threads' group-ch data visible; compute(ch-1) done by all
        if (ch < 6) {
            int st2 = (ch + 2) % 3;
            copyA(st2, ch + 2);
            copyB(st2, ch + 2);
            CP_COMMIT;
        }
        int st = ch % 3;
#pragma unroll
        for (int ks = 0; ks < 2; ks++) {
            int arow = wm * 64 + (lane & 15);
            int akc = ks * 16 + ((lane & 16) ? 8 : 0);
            int bkr = ks * 16 + (lane & 15);
            int bnc = wn * 32 + ((lane & 16) ? 8 : 0);

            uint32_t af[4][4], bh[8], bl[8];
#pragma unroll
            for (int mt = 0; mt < 4; mt++)
                LDSM_X4(af[mt], sptr(pA(sA, st, 0, arow + mt * 16) + akc));
            LDSM_X4_T(bh,     sptr(pB(sB, st, 0, bkr) + bnc));
            LDSM_X4_T(bh + 4, sptr(pB(sB, st, 0, bkr) + bnc + 16));
            LDSM_X4_T(bl,     sptr(pB(sB, st, 1, bkr) + bnc));
            LDSM_X4_T(bl + 4, sptr(pB(sB, st, 1, bkr) + bnc + 16));

#pragma unroll
            for (int mt = 0; mt < 4; mt++) {
#pragma unroll
                for (int nt = 0; nt < 4; nt++) {
                    mma16816(acc[mt][nt], af[mt], bh[nt * 2], bh[nt * 2 + 1]);
                    mma16816(acc[mt][nt], af[mt], bl[nt * 2], bl[nt * 2 + 1]);
                }
            }
#pragma unroll
            for (int mt = 0; mt < 4; mt++)
                LDSM_X4(af[mt], sptr(pA(sA, st, 1, arow + mt * 16) + akc));
#pragma unroll
            for (int mt = 0; mt < 4; mt++) {
#pragma unroll
                for (int nt = 0; nt < 4; nt++)
                    mma16816(acc[mt][nt], af[mt], bh[nt * 2], bh[nt * 2 + 1]);
            }
        }
    }
}

// MODE 10: fused pool/emb; MODE 0: fp32 store.
template <int MODE>
__global__ __launch_bounds__(256, 2) void bf_gemm(
    const __nv_bfloat16* __restrict__ Ah, const __nv_bfloat16* __restrict__ Al,
    const __nv_bfloat16* __restrict__ WhA, const __nv_bfloat16* __restrict__ WlA,
    const float* __restrict__ biasA,
    const __nv_bfloat16* __restrict__ WhB, const __nv_bfloat16* __restrict__ WlB,
    const float* __restrict__ biasB,
    float* __restrict__ Cout,
    unsigned* __restrict__ keyP, const int* __restrict__ segP,
    unsigned long long* __restrict__ keyE, const int* __restrict__ segE,
    int M)
{
    extern __shared__ char dsm[];
    int t = threadIdx.x, wid = t >> 5, lane = t & 31;
    int wm = wid >> 2, wn = wid & 3;
    int m0 = blockIdx.y * 128;

    bool isPool = false;
    const __nv_bfloat16 *Whp = WhA, *Wlp = WlA;
    const float* bp = biasA;
    int c0;
    if (MODE == 10) {
        isPool = ((blockIdx.x >> 1) == 0);
        if (!isPool) { Whp = WhB; Wlp = WlB; bp = biasB; }
        c0 = (blockIdx.x & 1) * 128;
    } else {
        c0 = blockIdx.x * 128;
    }

    float acc[4][4][4] = {};
    gemm_core(dsm, t, Ah, Al, Whp, Wlp, m0, c0, M, acc);

    int g = lane >> 2, tid4 = lane & 3;
#pragma unroll
    for (int mt = 0; mt < 4; mt++) {
#pragma unroll
        for (int nt = 0; nt < 4; nt++) {
            int coln = c0 + wn * 32 + nt * 8 + tid4 * 2;
            float b0 = bp[coln], b1 = bp[coln + 1];
#pragma unroll
            for (int half = 0; half < 2; half++) {
                int m = m0 + wm * 64 + mt * 16 + g + half * 8;
                if (m >= M) continue;
                float v0 = acc[mt][nt][half * 2 + 0] + b0;
                float v1 = acc[mt][nt][half * 2 + 1] + b1;
                if (MODE == 0) {
                    Cout[(size_t)m * 256 + coln]     = v0;
                    Cout[(size_t)m * 256 + coln + 1] = v1;
                } else {
                    if (isPool) {
                        int sg = segP[m];
                        atomicMax(&keyP[sg * 256 + coln],     fenc(v0));
                        atomicMax(&keyP[sg * 256 + coln + 1], fenc(v1));
                    } else {
                        int sg = segE[m];
                        unsigned long long p0 = ((unsigned long long)fenc(v0) << 32) | (unsigned)m;
                        unsigned long long p1 = ((unsigned long long)fenc(v1) << 32) | (unsigned)m;
                        atomicMax(&keyE[sg * 256 + coln],     p0);
                        atomicMax(&keyE[sg * 256 + coln + 1], p1);
                    }
                }
            }
        }
    }
}

// ---------------- merged Q+K+V projection (one launch) ----------------
#define QBLKS 338
__global__ __launch_bounds__(256, 2) void qkvproj_k(float qscale) {
    extern __shared__ char dsm[];
    int t = threadIdx.x, wid = t >> 5, lane = t & 31;
    int wm = wid >> 2, wn = wid & 3;
    int bx = blockIdx.x;

    const __nv_bfloat16 *Ahp, *Alp, *Whp, *Wlp;
    const float* bp;
    int m0, c0, M, mode;
    if (bx < QBLKS) {
        mode = 0;
        m0 = (bx >> 1) * 128;
        c0 = (bx & 1) * 128;
        Ahp = g_qinH; Alp = g_qinL;
        Whp = g_wH + 2 * 65536; Wlp = g_wL + 2 * 65536;
        bp = g_bq;
        M = SQ;
    } else {
        int r = bx - QBLKS;
        int sub = r & 3;
        int isV = sub >> 1;
        mode = 1 + isV;
        m0 = (r >> 2) * 128;
        c0 = (sub & 1) * 128;
        Ahp = g_kvH; Alp = g_kvL;
        Whp = g_wH + (3 + isV) * 65536;
        Wlp = g_wL + (3 + isV) * 65536;
        bp = isV ? g_bv : g_bk;
        M = SK;
    }

    float acc[4][4][4] = {};
    gemm_core(dsm, t, Ahp, Alp, Whp, Wlp, m0, c0, M, acc);

    int g = lane >> 2, tid4 = lane & 3;
#pragma unroll
    for (int mt = 0; mt < 4; mt++) {
#pragma unroll
        for (int nt = 0; nt < 4; nt++) {
            int coln = c0 + wn * 32 + nt * 8 + tid4 * 2;
            float b0 = bp[coln], b1 = bp[coln + 1];
#pragma unroll
            for (int half = 0; half < 2; half++) {
                int m = m0 + wm * 64 + mt * 16 + g + half * 8;
                if (m >= M) continue;
                float v0 = acc[mt][nt][half * 2 + 0] + b0;
                float v1 = acc[mt][nt][half * 2 + 1] + b1;
                if (mode == 0) {
                    uint32_t hi, lo;
                    split2pack(v0 * qscale, v1 * qscale, hi, lo);
                    *(uint32_t*)&g_qpH[(size_t)m * 256 + coln] = hi;
                    *(uint32_t*)&g_qpL[(size_t)m * 256 + coln] = lo;
                } else if (mode == 1) {
                    int b_ = m / 576, key = m - b_ * 576;
                    int hh = coln >> 5, d = coln & 31;
                    __nv_bfloat16 H, L;
                    split_bf16(v0, H, L);
                    size_t dst0 = (size_t)((b_ * 8 + hh) * 32 + d) * 576 + key;
                    g_k16h[dst0] = H; g_k16l[dst0] = L;
                    split_bf16(v1, H, L);
                    g_k16h[dst0 + 576] = H; g_k16l[dst0 + 576] = L;
                } else {
                    int b_ = m / 576, key = m - b_ * 576;
                    int hh = coln >> 5, d = coln & 31;
                    __nv_bfloat16 H, L;
                    size_t dst0 = ((size_t)(b_ * 8 + hh) * 576 + key) * 32 + d;
                    split_bf16(v0, H, L);
                    g_v16h[dst0] = H; g_v16l[dst0] = L;
                    split_bf16(v1, H, L);
                    g_v16h[dst0 + 1] = H; g_v16l[dst0 + 1] = L;
                }
            }
        }
    }
}

// ---------------- sine PE ----------------
__device__ __forceinline__ float pe_val(float cz, float cy, float cx, int c) {
    if (c >= PEC) return 0.f;
    int axis = c / (2 * NF);
    int r = c - axis * (2 * NF);
    int j = r < NF ? r : r - NF;
    float coord = (axis == 0) ? cz : (axis == 1) ? cy : cx;
    float spd = (axis == 0) ? 480.f : (axis == 1) ? 360.f : 32.f;
    float ang = coord / spd * 6.283185307179586f * g_invt[j];
    return (r < NF) ? __sinf(ang) : __cosf(ang);
}

// ---------------- merged build ----------------
__global__ void build_k(const int* __restrict__ ind) {
    int bx = blockIdx.x;
    int c = threadIdx.x;
    if (bx < SQ) {
        int s = bx;
        int rem = s % GQ;
        float cz = (float)((rem / (YD * XD)) * 8);
        float cy = (float)(((rem / XD) % YD) * 8);
        float cx = (float)((rem % XD) * 8);
        float base = g_mask_q[s] ? fdec(g_pool_key[(size_t)s * 256 + c]) : 0.f;
        float val = base + pe_val(cz, cy, cx, c);
        size_t idx = (size_t)s * 256 + c;
        __nv_bfloat16 h, l;
        split_bf16(val, h, l);
        g_qinH[idx] = h;
        g_qinL[idx] = l;
    } else {
        __shared__ float rz[256], ry[256], rx[256];
        int s = bx - SQ;
        unsigned long long key = g_emb_key[s * 256 + c];
        int i = (int)(key & 0xFFFFFFFFull);
        int z = ind[i * 4 + 1], y = ind[i * 4 + 2], x = ind[i * 4 + 3];
        rz[c] = (float)(z / 40);
        ry[c] = (float)(y / 15);
        rx[c] = (float)(x / 16);
        __syncthreads();
        for (int o = 128; o > 0; o >>= 1) {
            if (c < o) { rz[c] += rz[c + o]; ry[c] += ry[c + o]; rx[c] += rx[c + o]; }
            __syncthreads();
        }
        float cz = rz[0] * (1.f / 256.f) * 40.f;
        float cy = ry[0] * (1.f / 256.f) * 15.f;
        float cx = rx[0] * (1.f / 256.f) * 16.f;
        float base = g_mask_k[s] ? fdec((unsigned)(key >> 32)) : 0.f;
        float val = base + pe_val(cz, cy, cx, c);
        __nv_bfloat16 h, l;
        split_bf16(val, h, l);
        g_kvH[s * 256 + c] = h;
        g_kvL[s * 256 + c] = l;
    }
}

// ---------------- fused flash attention (64-key chunks, 1 barrier/chunk) ----------------
#define QPAD 40
#define KPAD 72
#define FQ_BYTES (2 * 128 * QPAD * 2)
#define FK_BYTES (2 * 2 * 32 * KPAD * 2)
#define FV_BYTES (2 * 2 * 64 * QPAD * 2)
#define FATTN_SMEM (FQ_BYTES + FK_BYTES + FV_BYTES + GK * 4)

__global__ __launch_bounds__(256) void fattn_k(const int* __restrict__ maskk) {
    extern __shared__ char fsm[];
    __nv_bfloat16* sQ = (__nv_bfloat16*)fsm;
    __nv_bfloat16* sK = (__nv_bfloat16*)(fsm + FQ_BYTES);
    __nv_bfloat16* sV = (__nv_bfloat16*)(fsm + FQ_BYTES + FK_BYTES);
    int* smask = (int*)(fsm + FQ_BYTES + FK_BYTES + FV_BYTES);

    int t = threadIdx.x, wid = t >> 5, lane = t & 31;
    int bh = blockIdx.y, b = bh >> 3, h = bh & 7;
    int q0 = blockIdx.x * 128;

    auto sQp = [&](int hl, int r) { return sQ + (hl * 128 + r) * QPAD; };
    auto sKp = [&](int st, int hl, int d) { return sK + ((st * 2 + hl) * 32 + d) * KPAD; };
    auto sVp = [&](int st, int hl, int k) { return sV + ((st * 2 + hl) * 64 + k) * QPAD; };

    auto copyKV = [&](int c, int st) {
        int d = t >> 3, ks = (t & 7) * 8;
        size_t srck = (size_t)(bh * 32 + d) * 576 + c * 64 + ks;
        CP16(sptr(sKp(st, 0, d) + ks), g_k16h + srck);
        CP16(sptr(sKp(st, 1, d) + ks), g_k16l + srck);
        int key = t >> 2, ds = (t & 3) * 8;
        size_t srcv = (size_t)(bh * 576 + c * 64 + key) * 32 + ds;
        CP16(sptr(sVp(st, 0, key) + ds), g_v16h + srcv);
        CP16(sptr(sVp(st, 1, key) + ds), g_v16l + srcv);
    };

    copyKV(0, 0);
    CP_COMMIT;

    {
#pragma unroll
        for (int i = 0; i < 2; i++) {
            int op = t * 2 + i;
            int r = op >> 2, seg = op & 3;
            uint4 vh = make_uint4(0, 0, 0, 0), vl = vh;
            if (q0 + r < GQ) {
                size_t s = (size_t)(b * GQ + q0 + r) * 256 + h * 32 + seg * 8;
                vh = *(const uint4*)&g_qpH[s];
                vl = *(const uint4*)&g_qpL[s];
            }
            *(uint4*)(sQp(0, r) + seg * 8) = vh;
            *(uint4*)(sQp(1, r) + seg * 8) = vl;
        }
    }
    for (int i = t; i < GK; i += 256) smask[i] = maskk[b * GK + i];
    __syncthreads();

    uint32_t qh[2][4], ql[2][4];
    {
        int arow = wid * 16 + (lane & 15);
#pragma unroll
        for (int s = 0; s < 2; s++) {
            int akc = s * 16 + ((lane & 16) ? 8 : 0);
            LDSM_X4(qh[s], sptr(sQp(0, arow) + akc));
            LDSM_X4(ql[s], sptr(sQp(1, arow) + akc));
        }
    }

    float m0r = -INFINITY, m1r = -INFINITY, l0 = 0.f, l1 = 0.f;
    float oacc[4][4] = {};
    int g = lane >> 2, tid4 = lane & 3;
    int bkr = lane & 15;
    int bsel = (lane & 16) ? 8 : 0;

    for (int c = 0; c < 9; c++) {
        int st = c & 1;
        CP_WAIT0;          // group c complete (own copies)
        __syncthreads();   // all threads' stage-c data visible; compute(c-1) done by all
        if (c < 8) {
            copyKV(c + 1, st ^ 1);   // overwrites stage read in compute(c-1): safe post-barrier
            CP_COMMIT;
        }

        float acc[8][4] = {};
#pragma unroll
        for (int s = 0; s < 2; s++) {
#pragma unroll
            for (int j = 0; j < 4; j++) {
                uint32_t kh_[4], kl_[4];
                LDSM_X4_T(kh_, sptr(sKp(st, 0, s * 16 + bkr) + j * 16 + bsel));
                LDSM_X4_T(kl_, sptr(sKp(st, 1, s * 16 + bkr) + j * 16 + bsel));
                mma16816(acc[2 * j],     qh[s], kh_[0], kh_[1]);
                mma16816(acc[2 * j],     qh[s], kl_[0], kl_[1]);
                mma16816(acc[2 * j],     ql[s], kh_[0], kh_[1]);
                mma16816(acc[2 * j + 1], qh[s], kh_[2], kh_[3]);
                mma16816(acc[2 * j + 1], qh[s], kl_[2], kl_[3]);
                mma16816(acc[2 * j + 1], ql[s], kh_[2], kh_[3]);
            }
        }
#pragma unroll
        for (int j = 0; j < 8; j++) {
            int key = c * 64 + j * 8 + tid4 * 2;
            if (!smask[key])     { acc[j][0] = -1e9f; acc[j][2] = -1e9f; }
            if (!smask[key + 1]) { acc[j][1] = -1e9f; acc[j][3] = -1e9f; }
        }
        float mx0 = -INFINITY, mx1 = -INFINITY;
#pragma unroll
        for (int j = 0; j < 8; j++) {
            mx0 = fmaxf(mx0, fmaxf(acc[j][0], acc[j][1]));
            mx1 = fmaxf(mx1, fmaxf(acc[j][2], acc[j][3]));
        }
        mx0 = fmaxf(mx0, __shfl_xor_sync(0xFFFFFFFFu, mx0, 1));
        mx0 = fmaxf(mx0, __shfl_xor_sync(0xFFFFFFFFu, mx0, 2));
        mx1 = fmaxf(mx1, __shfl_xor_sync(0xFFFFFFFFu, mx1, 1));
        mx1 = fmaxf(mx1, __shfl_xor_sync(0xFFFFFFFFu, mx1, 2));
        float mn0 = fmaxf(m0r, mx0), mn1 = fmaxf(m1r, mx1);
        float rs0 = __expf(m0r - mn0), rs1 = __expf(m1r - mn1);
        float sum0 = 0.f, sum1 = 0.f;
#pragma unroll
        for (int j = 0; j < 8; j++) {
            acc[j][0] = __expf(acc[j][0] - mn0);
            acc[j][1] = __expf(acc[j][1] - mn0);
            acc[j][2] = __expf(acc[j][2] - mn1);
            acc[j][3] = __expf(acc[j][3] - mn1);
            sum0 += acc[j][0] + acc[j][1];
            sum1 += acc[j][2] + acc[j][3];
        }
        sum0 += __shfl_xor_sync(0xFFFFFFFFu, sum0, 1);
        sum0 += __shfl_xor_sync(0xFFFFFFFFu, sum0, 2);
        sum1 += __shfl_xor_sync(0xFFFFFFFFu, sum1, 1);
        sum1 += __shfl_xor_sync(0xFFFFFFFFu, sum1, 2);
        l0 = l0 * rs0 + sum0;
        l1 = l1 * rs1 + sum1;
#pragma unroll
        for (int dt = 0; dt < 4; dt++) {
            oacc[dt][0] *= rs0; oacc[dt][1] *= rs0;
            oacc[dt][2] *= rs1; oacc[dt][3] *= rs1;
        }
        m0r = mn0; m1r = mn1;

#pragma unroll
        for (int kt = 0; kt < 4; kt++) {
            uint32_t pha[4], pla[4];
            split2pack(acc[2 * kt][0],     acc[2 * kt][1],     pha[0], pla[0]);
            split2pack(acc[2 * kt][2],     acc[2 * kt][3],     pha[1], pla[1]);
            split2pack(acc[2 * kt + 1][0], acc[2 * kt + 1][1], pha[2], pla[2]);
            split2pack(acc[2 * kt + 1][2], acc[2 * kt + 1][3], pha[3], pla[3]);
#pragma unroll
            for (int dh2 = 0; dh2 < 2; dh2++) {
                uint32_t vh_[4], vl_[4];
                LDSM_X4_T(vh_, sptr(sVp(st, 0, kt * 16 + bkr) + dh2 * 16 + bsel));
                LDSM_X4_T(vl_, sptr(sVp(st, 1, kt * 16 + bkr) + dh2 * 16 + bsel));
                mma16816(oacc[dh2 * 2],     pha, vh_[0], vh_[1]);
                mma16816(oacc[dh2 * 2],     pha, vl_[0], vl_[1]);
                mma16816(oacc[dh2 * 2],     pla, vh_[0], vh_[1]);
                mma16816(oacc[dh2 * 2 + 1], pha, vh_[2], vh_[3]);
                mma16816(oacc[dh2 * 2 + 1], pha, vl_[2], vl_[3]);
                mma16816(oacc[dh2 * 2 + 1], pla, vh_[2], vh_[3]);
            }
        }
    }

    float inv0 = 1.f / l0, inv1 = 1.f / l1;
    int qa = q0 + wid * 16 + g;
    int qb = qa + 8;
#pragma unroll
    for (int dt = 0; dt < 4; dt++) {
        int dim = h * 32 + dt * 8 + tid4 * 2;
        if (qa < GQ) {
            uint32_t hi, lo;
            split2pack(oacc[dt][0] * inv0, oacc[dt][1] * inv0, hi, lo);
            *(uint32_t*)&g_oaH[(size_t)(b * GQ + qa) * 256 + dim] = hi;
            *(uint32_t*)&g_oaL[(size_t)(b * GQ + qa) * 256 + dim] = lo;
        }
        if (qb < GQ) {
            uint32_t hi, lo;
            split2pack(oacc[dt][2] * inv1, oacc[dt][3] * inv1, hi, lo);
            *(uint32_t*)&g_oaH[(size_t)(b * GQ + qb) * 256 + dim] = hi;
            *(uint32_t*)&g_oaL[(size_t)(b * GQ + qb) * 256 + dim] = lo;
        }
    }
}

// ---------------- residual + LayerNorm ----------------
__global__ void ln_k(const float* __restrict__ o2,
                     const float* __restrict__ g, const float* __restrict__ bb,
                     float* __restrict__ out) {
    __shared__ float red[256];
    __shared__ float mu_s, var_s;
    int r = blockIdx.x;
    int c = threadIdx.x;
    size_t idx = (size_t)r * 256 + c;
    float qv = __bfloat162float(g_qinH[idx]) + __bfloat162float(g_qinL[idx]);
    float h = qv + o2[idx];
    red[c] = h;
    __syncthreads();
    for (int o = 128; o > 0; o >>= 1) {
        if (c < o) red[c] += red[c + o];
        __syncthreads();
    }
    if (c == 0) mu_s = red[0] * (1.f / 256.f);
    __syncthreads();
    float d = h - mu_s;
    red[c] = d * d;
    __syncthreads();
    for (int o = 128; o > 0; o >>= 1) {
        if (c < o) red[c] += red[c + o];
        __syncthreads();
    }
    if (c == 0) var_s = red[0] * (1.f / 256.f);
    __syncthreads();
    out[idx] = d * rsqrtf(var_s + 1e-5f) * g[c] + bb[c];
}

__global__ void head_k(const float* __restrict__ feat, const float* __restrict__ Wseg,
                       const float* __restrict__ bseg, float* __restrict__ out) {
    __shared__ float Ws[256 * NOUT];
    int t = threadIdx.x;
    for (int i = t; i < 256 * NOUT; i += 256) Ws[i] = Wseg[i];
    __syncthreads();
    int p = blockIdx.x * 8 + (t >> 5);
    int lane = t & 31;
    int sg = g_segq[p];
    float v[8];
#pragma unroll
    for (int r = 0; r < 8; r++) {
        int c = lane + 32 * r;
        v[r] = feat[(size_t)p * 256 + c] + g_mhca[(size_t)sg * 256 + c];
    }
#pragma unroll
    for (int j = 0; j < NOUT; j++) {
        float s = 0.f;
#pragma unroll
        for (int r = 0; r < 8; r++) s = fmaf(v[r], Ws[(lane + 32 * r) * NOUT + j], s);
#pragma unroll
        for (int o = 16; o; o >>= 1) s += __shfl_xor_sync(0xFFFFFFFFu, s, o);
        if (lane == 0) out[(size_t)p * NOUT + j] = s + bseg[j];
    }
}

static void* sym_addr(const void* symbol) {
    void* p = nullptr;
    cudaGetSymbolAddress(&p, symbol);
    return p;
}

extern "C" void kernel_launch(void* const* d_in, const int* in_sizes, int n_in,
                              void* d_out, int out_size) {
    const float* feat  = (const float*)d_in[0];
    const float* Wpool = (const float*)d_in[1];
    const float* bpool = (const float*)d_in[2];
    const float* Wemb  = (const float*)d_in[3];
    const float* bemb  = (const float*)d_in[4];
    const float* Wq    = (const float*)d_in[5];
    const float* bq    = (const float*)d_in[6];
    const float* Wk    = (const float*)d_in[7];
    const float* bk    = (const float*)d_in[8];
    const float* Wv    = (const float*)d_in[9];
    const float* bv    = (const float*)d_in[10];
    const float* Wo    = (const float*)d_in[11];
    const float* bo    = (const float*)d_in[12];
    const float* lng   = (const float*)d_in[13];
    const float* lnb   = (const float*)d_in[14];
    const float* Wseg  = (const float*)d_in[15];
    const float* bseg  = (const float*)d_in[16];
    const int*   ind   = (const int*)d_in[17];
    float* out = (float*)d_out;

    unsigned* p_pool_key = (unsigned*)sym_addr(g_pool_key);
    unsigned long long* p_emb_key = (unsigned long long*)sym_addr(g_emb_key);
    int*      p_segq   = (int*)sym_addr(g_segq);
    int*      p_segk   = (int*)sym_addr(g_segk);
    int*      p_mask_q = (int*)sym_addr(g_mask_q);
    int*      p_mask_k = (int*)sym_addr(g_mask_k);
    float*    p_o2     = (float*)sym_addr(g_o2);
    float*    p_mhca   = (float*)sym_addr(g_mhca);
    __nv_bfloat16* p_featH = (__nv_bfloat16*)sym_addr(g_featH);
    __nv_bfloat16* p_featL = (__nv_bfloat16*)sym_addr(g_featL);
    __nv_bfloat16* p_wH    = (__nv_bfloat16*)sym_addr(g_wH);
    __nv_bfloat16* p_wL    = (__nv_bfloat16*)sym_addr(g_wL);
    __nv_bfloat16* p_oaH   = (__nv_bfloat16*)sym_addr(g_oaH);
    __nv_bfloat16* p_oaL   = (__nv_bfloat16*)sym_addr(g_oaL);

    cudaFuncSetAttribute(bf_gemm<10>, cudaFuncAttributeMaxDynamicSharedMemorySize, GEMM_SMEM);
    cudaFuncSetAttribute(bf_gemm<0>,  cudaFuncAttributeMaxDynamicSharedMemorySize, GEMM_SMEM);
    cudaFuncSetAttribute(qkvproj_k,   cudaFuncAttributeMaxDynamicSharedMemorySize, GEMM_SMEM);
    cudaFuncSetAttribute(fattn_k, cudaFuncAttributeMaxDynamicSharedMemorySize, FATTN_SMEM);

    const float qscale = 0.17677669529663687f;

    // 0. memsets
    cudaMemsetAsync(p_pool_key, 0, (size_t)SQ * DIM * 4);
    cudaMemsetAsync(p_emb_key, 0, (size_t)SK * DIM * 8);
    cudaMemsetAsync(p_mask_q, 0, SQ * 4);
    cudaMemsetAsync(p_mask_k, 0, SK * 4);
    // 1. splits + biases + PE table + prep (one launch)
    split_prep_k<<<FEAT_BLOCKS + W_BLOCKS + 1 + PREP_BLOCKS, 256>>>(
        feat, Wpool, Wemb, Wq, Wk, Wv, Wo, bq, bk, bv, ind);
    // 2. fused pool+emb GEMM (value scatter + packed argmax)
    bf_gemm<10><<<dim3(4, (NP + 127) / 128), 256, GEMM_SMEM>>>(
        p_featH, p_featL,
        p_wH + 0 * 65536, p_wL + 0 * 65536, bpool,
        p_wH + 1 * 65536, p_wL + 1 * 65536, bemb,
        nullptr, p_pool_key, p_segq, p_emb_key, p_segk, NP);
    // 3. merged PE-grid build
    build_k<<<SQ + SK, 256>>>(ind);
    // 4. merged Q+K+V projections
    qkvproj_k<<<QBLKS + 36, 256, GEMM_SMEM>>>(qscale);
    // 5. fused flash attention (64-key chunks, single-barrier pipeline)
    fattn_k<<<dim3((GQ + 127) / 128, BATCH * NH), 256, FATTN_SMEM>>>(p_mask_k);
    // 6. output projection + residual + LN
    bf_gemm<0><<<dim3(2, (SQ + 127) / 128), 256, GEMM_SMEM>>>(
        p_oaH, p_oaL, p_wH + 5 * 65536, p_wL + 5 * 65536, bo,
        nullptr, nullptr, nullptr, p_o2, nullptr, nullptr, nullptr, nullptr, SQ);
    ln_k<<<SQ, 256>>>(p_o2, lng, lnb, p_mhca);
    // 7. gather + seg head
    head_k<<<NP / 8, 256>>>(feat, Wseg, bseg, out);
}